// round 12
// baseline (speedup 1.0000x reference)
#include <cuda_runtime.h>
#include <cuda_bf16.h>
#include <math.h>
#include <stdint.h>

typedef unsigned long long ull;

#define NBATCH 1024
#define SEQL   200
#define DIM    256
#define NCAPS  8

#if !defined(__CUDA_ARCH__) || defined(__CUDA_ARCH_FEAT_SM103_ALL) || \
    defined(__CUDA_ARCH_FEAT_SM100_ALL) || defined(__CUDA_ARCH_FEAT_SM101_ALL)
#define TC_OK 1
#else
#define TC_OK 0
#endif

// ---------------- device scratch (no allocations allowed) ----------------
__device__ float g_mapped[(size_t)NBATCH * SEQL * DIM];   // 209.7 MB
__device__ float g_logits[NCAPS * SEQL];                  // 6.4 KB
__device__ float g_part[(size_t)NCAPS * SEQL * NBATCH];   // [k*L][b]
__device__ __nv_bfloat16 g_WhT[DIM * DIM];
__device__ __nv_bfloat16 g_WlT[DIM * DIM];

// ---------------- f32x2 helpers ------------------------------------------
__device__ __forceinline__ ull ffma2(ull a, ull b, ull c) {
    ull d;
    asm("fma.rn.f32x2 %0, %1, %2, %3;" : "=l"(d) : "l"(a), "l"(b), "l"(c));
    return d;
}
__device__ __forceinline__ ull dup2(float x) {
    ull d;
    asm("mov.b64 %0, {%1, %1};" : "=l"(d) : "f"(x));
    return d;
}
__device__ __forceinline__ float2 unpack2(ull a) {
    float2 f;
    asm("mov.b64 {%0, %1}, %2;" : "=f"(f.x), "=f"(f.y) : "l"(a));
    return f;
}

// ---------------- smem/mbarrier/TMA helpers (baseline PTX) ----------------
__device__ __forceinline__ uint32_t smem_u32(const void* p) {
    uint32_t a;
    asm("{ .reg .u64 t; cvta.to.shared.u64 t, %1; cvt.u32.u64 %0, t; }"
        : "=r"(a) : "l"(p));
    return a;
}
__device__ __forceinline__ void mbar_init(uint32_t a, uint32_t cnt) {
    asm volatile("mbarrier.init.shared.b64 [%0], %1;" :: "r"(a), "r"(cnt) : "memory");
}
__device__ __forceinline__ void mbar_expect_tx(uint32_t a, uint32_t bytes) {
    asm volatile("mbarrier.arrive.expect_tx.shared.b64 _, [%0], %1;"
                 :: "r"(a), "r"(bytes) : "memory");
}
__device__ __forceinline__ void tma_1d(uint32_t dst, const void* src,
                                       uint32_t bytes, uint32_t mbar) {
    asm volatile(
        "cp.async.bulk.shared::cluster.global.mbarrier::complete_tx::bytes "
        "[%0], [%1], %2, [%3];"
        :: "r"(dst), "l"(src), "r"(bytes), "r"(mbar) : "memory");
}
__device__ __forceinline__ void mbar_wait(uint32_t a, uint32_t par) {
    asm volatile(
        "{\n\t.reg .pred P;\n"
        "W%=:\n\t"
        "mbarrier.try_wait.parity.acquire.cta.shared::cta.b64 P, [%0], %1, 0x989680;\n\t"
        "@P bra D%=;\n\t"
        "bra W%=;\n"
        "D%=:\n\t}" :: "r"(a), "r"(par) : "memory");
}

#if TC_OK
__device__ __forceinline__ uint32_t elect1() {
    uint32_t p;
    asm volatile("{ .reg .pred p; elect.sync _|p, 0xFFFFFFFF; selp.b32 %0,1,0,p; }"
                 : "=r"(p));
    return p;
}
__device__ __forceinline__ void mma_f16_ss(uint32_t d, uint64_t a, uint64_t b,
                                           uint32_t id, uint32_t en) {
    asm volatile(
        "{\n\t.reg .pred p;\n\tsetp.ne.u32 p, %5, 0;\n\t"
        "tcgen05.mma.cta_group::1.kind::f16 [%0], %1, %2, %3, {%4,%4,%4,%4}, p;\n\t}"
        :: "r"(d), "l"(a), "l"(b), "r"(id), "r"(0u), "r"(en) : "memory");
}
#define LDTM_X32(r, addr) \
    asm volatile( \
        "tcgen05.ld.sync.aligned.32x32b.x32.b32 " \
        "{%0,%1,%2,%3,%4,%5,%6,%7,%8,%9,%10,%11,%12,%13,%14,%15," \
        "%16,%17,%18,%19,%20,%21,%22,%23,%24,%25,%26,%27,%28,%29,%30,%31}, [%32];" \
        : "=r"((r)[0]),"=r"((r)[1]),"=r"((r)[2]),"=r"((r)[3]), \
          "=r"((r)[4]),"=r"((r)[5]),"=r"((r)[6]),"=r"((r)[7]), \
          "=r"((r)[8]),"=r"((r)[9]),"=r"((r)[10]),"=r"((r)[11]), \
          "=r"((r)[12]),"=r"((r)[13]),"=r"((r)[14]),"=r"((r)[15]), \
          "=r"((r)[16]),"=r"((r)[17]),"=r"((r)[18]),"=r"((r)[19]), \
          "=r"((r)[20]),"=r"((r)[21]),"=r"((r)[22]),"=r"((r)[23]), \
          "=r"((r)[24]),"=r"((r)[25]),"=r"((r)[26]),"=r"((r)[27]), \
          "=r"((r)[28]),"=r"((r)[29]),"=r"((r)[30]),"=r"((r)[31]) \
        : "r"(addr))
#endif  // TC_OK

// ---------------- init kernels -------------------------------------------
__global__ void k_init(const float* __restrict__ rlog) {
    int i = blockIdx.x * blockDim.x + threadIdx.x;
    if (i < NCAPS * SEQL) g_logits[i] = rlog[i];
}

__global__ void k_convW(const float* __restrict__ W) {
    int k = blockIdx.x;
    int n = threadIdx.x;
    float v = W[k * DIM + n];
    __nv_bfloat16 h = __float2bfloat16(v);
    float r = v - __bfloat162float(h);
    g_WhT[n * DIM + k] = h;
    g_WlT[n * DIM + k] = __float2bfloat16(r);
}

// ---------------- tensor-core GEMM: g_mapped = A @ W ----------------------
#define OFF_AH 1024
#define OFF_AL 17408
#define OFF_BH 33792
#define OFF_BL 66560
#define GSM_BYTES 99328

__global__ __launch_bounds__(256, 2) void k_gemm_tc(const float* __restrict__ A,
                                                    const float* __restrict__ W) {
#if TC_OK
    extern __shared__ __align__(16) float sm[];
    char* sb = (char*)sm;
    uint32_t sbase = smem_u32(sm);
    int tid = threadIdx.x, wid = tid >> 5;
    size_t m0 = (size_t)blockIdx.x * 128;

    if (wid == 0) {
        asm volatile("tcgen05.alloc.cta_group::1.sync.aligned.shared::cta.b32 [%0], %1;"
                     :: "r"(sbase), "r"(256u) : "memory");
        asm volatile("tcgen05.relinquish_alloc_permit.cta_group::1.sync.aligned;");
    }
    __syncthreads();
    uint32_t tb;
    asm volatile("ld.shared.b32 %0, [%1];" : "=r"(tb) : "r"(sbase));

    if (tid == 0) mbar_init(sbase + 8, 1u);
    __syncthreads();

    const uint64_t DB = (2ULL << 61) | (1ULL << 46) | (64ULL << 32) | (1ULL << 16);
    uint64_t dAh = DB | (((uint64_t)(sbase + OFF_AH) >> 4) & 0x3FFF);
    uint64_t dAl = DB | (((uint64_t)(sbase + OFF_AL) >> 4) & 0x3FFF);
    uint64_t dBh = DB | (((uint64_t)(sbase + OFF_BH) >> 4) & 0x3FFF);
    uint64_t dBl = DB | (((uint64_t)(sbase + OFF_BL) >> 4) & 0x3FFF);
    const uint32_t idesc = (1u << 4) | (1u << 7) | (1u << 10) |
                           ((DIM / 8) << 17) | ((128 / 16) << 24);

    float4 fA[8];
#pragma unroll
    for (int i = 0; i < 8; i++) {
        int idx = tid + i * 256;
        int r = idx >> 4, c4 = idx & 15;
        fA[i] = *(const float4*)(A + (m0 + r) * DIM + 0 + c4 * 4);
    }

    uint32_t first = 0;
    for (int c = 0; c < 4; c++) {
        int k0 = c * 64;
#pragma unroll
        for (int i = 0; i < 8; i++) {
            int idx = tid + i * 256;
            int r = idx >> 4, c4 = idx & 15;
            float4 f = fA[i];
            __nv_bfloat16 h0 = __float2bfloat16(f.x), h1 = __float2bfloat16(f.y),
                          h2 = __float2bfloat16(f.z), h3 = __float2bfloat16(f.w);
            float l0 = f.x - __bfloat162float(h0), l1 = f.y - __bfloat162float(h1),
                  l2 = f.z - __bfloat162float(h2), l3 = f.w - __bfloat162float(h3);
            uint32_t off = r * 128 + c4 * 8;
            uint32_t sw = off ^ ((off >> 3) & 0x70);
            uint2 uh, ulv;
            uh.x = ((uint32_t)__bfloat16_as_ushort(h1) << 16) | __bfloat16_as_ushort(h0);
            uh.y = ((uint32_t)__bfloat16_as_ushort(h3) << 16) | __bfloat16_as_ushort(h2);
            __nv_bfloat16 q0 = __float2bfloat16(l0), q1 = __float2bfloat16(l1),
                          q2 = __float2bfloat16(l2), q3 = __float2bfloat16(l3);
            ulv.x = ((uint32_t)__bfloat16_as_ushort(q1) << 16) | __bfloat16_as_ushort(q0);
            ulv.y = ((uint32_t)__bfloat16_as_ushort(q3) << 16) | __bfloat16_as_ushort(q2);
            *(uint2*)(sb + OFF_AH + sw) = uh;
            *(uint2*)(sb + OFF_AL + sw) = ulv;
        }
#pragma unroll
        for (int i = 0; i < 8; i++) {
            int idx = tid + i * 256;
            int r = idx >> 3, cc = idx & 7;
            uint32_t off = r * 128 + cc * 16;
            uint32_t sw = off ^ ((off >> 3) & 0x70);
            uint4 vh = *(const uint4*)((const char*)g_WhT + r * 512 + k0 * 2 + cc * 16);
            uint4 vl = *(const uint4*)((const char*)g_WlT + r * 512 + k0 * 2 + cc * 16);
            *(uint4*)(sb + OFF_BH + sw) = vh;
            *(uint4*)(sb + OFF_BL + sw) = vl;
        }
        __syncthreads();
        if (wid == 0) {
            asm volatile("fence.proxy.async.shared::cta;" ::: "memory");
            if (elect1()) {
#pragma unroll
                for (int s = 0; s < 4; s++) {
                    mma_f16_ss(tb, dAh + s * 2, dBh + s * 2, idesc, first);
                    first = 1;
                    mma_f16_ss(tb, dAh + s * 2, dBl + s * 2, idesc, 1);
                    mma_f16_ss(tb, dAl + s * 2, dBh + s * 2, idesc, 1);
                }
                asm volatile(
                    "tcgen05.commit.cta_group::1.mbarrier::arrive::one.shared::cluster.b64 [%0];"
                    :: "r"(sbase + 8) : "memory");
            }
        }
        if (c < 3) {
            int kn = k0 + 64;
#pragma unroll
            for (int i = 0; i < 8; i++) {
                int idx = tid + i * 256;
                int r = idx >> 4, c4 = idx & 15;
                fA[i] = *(const float4*)(A + (m0 + r) * DIM + kn + c4 * 4);
            }
        }
        mbar_wait(sbase + 8, (uint32_t)(c & 1));
    }

    asm volatile("tcgen05.fence::after_thread_sync;" ::: "memory");
    if (tid < 128) {
        float* Crow = g_mapped + (m0 + tid) * DIM;
#pragma unroll
        for (int j = 0; j < 8; j++) {
            uint32_t r[32];
            LDTM_X32(r, tb + j * 32);
            asm volatile("tcgen05.wait::ld.sync.aligned;" ::: "memory");
#pragma unroll
            for (int q = 0; q < 8; q++) {
                float4 v = make_float4(__uint_as_float(r[q * 4 + 0]),
                                       __uint_as_float(r[q * 4 + 1]),
                                       __uint_as_float(r[q * 4 + 2]),
                                       __uint_as_float(r[q * 4 + 3]));
                *(float4*)(Crow + j * 32 + q * 4) = v;
            }
        }
    }
    __syncthreads();
    if (wid == 0) {
        asm volatile("tcgen05.dealloc.cta_group::1.sync.aligned.b32 %0, %1;"
                     :: "r"(tb), "r"(256u));
    }
#else
    size_t m0 = (size_t)blockIdx.x * 128;
    int tid = threadIdx.x;
    for (int e = tid; e < 128 * 256; e += 256) {
        int r = e >> 8, n = e & 255;
        float acc = 0.f;
        for (int k = 0; k < DIM; k++)
            acc += A[(m0 + r) * DIM + k] * W[k * DIM + n];
        g_mapped[(m0 + r) * DIM + n] = acc;
    }
#endif
}

// ---------------- k_fusedp: PERSISTENT fused iteration --------------------
// grid=148; CTA loops batches b = bid, bid+148, ... Whole 200x256 tile
// resident in 13x16KB stages. Delta walks stages in order; after each stage
// is consumed, its TMA for the NEXT batch is issued -> loads of batch i+1
// overlap compute of batch i. Stage parity = per-CTA batch count & 1.
#define FR_NST  13
#define FR_RING 512
#define FR_W    (FR_RING + FR_NST * 16384)   // 213504
#define FR_CAPS (FR_W + SEQL * NCAPS * 4)    // 219904
#define FR_RED  (FR_CAPS + NCAPS * DIM * 4)  // 228096
#define FR_SC   (FR_RED + 256)               // 228352
#define FR_BYTES (FR_SC + 32)                // 228384

#define PGRID 148

__global__ __launch_bounds__(256, 1) void k_fusedp(const int* __restrict__ seq_len,
                                                   float* __restrict__ out) {
    extern __shared__ __align__(16) char dsm[];
    uint32_t sbase = smem_u32(dsm);
    float* ring   = (float*)(dsm + FR_RING);   // contiguous [200][256]
    float* sm_w   = (float*)(dsm + FR_W);
    float* sm_caps= (float*)(dsm + FR_CAPS);
    float* sm_red = (float*)(dsm + FR_RED);
    float* sm_sc  = (float*)(dsm + FR_SC);

    int tid = threadIdx.x;
    int warp = tid >> 5, lane = tid & 31;

    if (tid == 0) {
#pragma unroll
        for (int s = 0; s < FR_NST; s++) mbar_init(sbase + s * 8, 1u);
    }
    __syncthreads();

    // prologue: issue all 13 stages for the first batch
    int b0 = blockIdx.x;
    if (tid == 0 && b0 < NBATCH) {
        const float* mbp = g_mapped + (size_t)b0 * (SEQL * DIM);
#pragma unroll
        for (int s = 0; s < FR_NST; s++) {
            int rows = SEQL - s * 16; if (rows > 16) rows = 16;
            uint32_t bytes = (uint32_t)rows * 1024u;
            mbar_expect_tx(sbase + s * 8, bytes);
            tma_1d(sbase + FR_RING + s * 16384, mbp + (size_t)s * 16 * 256,
                   bytes, sbase + s * 8);
        }
    }

    int n = 0;  // per-CTA batch counter (stage parity = n & 1)
    for (int b = b0; b < NBATCH; b += PGRID, n++) {
        int seq = seq_len[b];
        uint32_t par = (uint32_t)(n & 1);

        // ---- masked softmax (sm_w safe: prior batch fully done) ----
        {
            int k = warp;
            float vals[7];
            float mx = -INFINITY;
#pragma unroll
            for (int j = 0; j < 7; j++) {
                int l = lane + 32 * j;
                float v = (l < seq) ? g_logits[k * SEQL + l] : -INFINITY;
                vals[j] = v;
                mx = fmaxf(mx, v);
            }
#pragma unroll
            for (int off = 16; off; off >>= 1)
                mx = fmaxf(mx, __shfl_xor_sync(0xffffffffu, mx, off));
            float s = 0.f;
#pragma unroll
            for (int j = 0; j < 7; j++) {
                float e = expf(vals[j] - mx);
                vals[j] = e;
                s += e;
            }
#pragma unroll
            for (int off = 16; off; off >>= 1)
                s += __shfl_xor_sync(0xffffffffu, s, off);
            float inv = 1.f / s;
#pragma unroll
            for (int j = 0; j < 7; j++) {
                int l = lane + 32 * j;
                if (l < SEQL) sm_w[l * NCAPS + k] = vals[j] * inv;
            }
        }
        __syncthreads();

        // ---- Z: consume stages as they land (no reuse within batch) ----
        int nblkZ = (seq + 15) >> 4;
        ull z2[4] = {0ULL, 0ULL, 0ULL, 0ULL};
        for (int blk = 0; blk < nblkZ; blk++) {
            mbar_wait(sbase + blk * 8, par);
            const float* st = ring + blk * 4096;
            int base = blk * 16;
            int rows = seq - base; if (rows > 16) rows = 16;
            if (rows == 16) {
#pragma unroll
                for (int r = 0; r < 16; r++) {
                    ull md = dup2(st[r * 256 + tid]);
                    ulonglong2 wa = *(const ulonglong2*)&sm_w[(base + r) * NCAPS];
                    ulonglong2 wb = *(const ulonglong2*)&sm_w[(base + r) * NCAPS + 4];
                    z2[0] = ffma2(md, wa.x, z2[0]);
                    z2[1] = ffma2(md, wa.y, z2[1]);
                    z2[2] = ffma2(md, wb.x, z2[2]);
                    z2[3] = ffma2(md, wb.y, z2[3]);
                }
            } else {
                for (int r = 0; r < rows; r++) {
                    ull md = dup2(st[r * 256 + tid]);
                    ulonglong2 wa = *(const ulonglong2*)&sm_w[(base + r) * NCAPS];
                    ulonglong2 wb = *(const ulonglong2*)&sm_w[(base + r) * NCAPS + 4];
                    z2[0] = ffma2(md, wa.x, z2[0]);
                    z2[1] = ffma2(md, wa.y, z2[1]);
                    z2[2] = ffma2(md, wb.x, z2[2]);
                    z2[3] = ffma2(md, wb.y, z2[3]);
                }
            }
        }

        float z[8];
        {
            float2 f;
            f = unpack2(z2[0]); z[0] = f.x; z[1] = f.y;
            f = unpack2(z2[1]); z[2] = f.x; z[3] = f.y;
            f = unpack2(z2[2]); z[4] = f.x; z[5] = f.y;
            f = unpack2(z2[3]); z[6] = f.x; z[7] = f.y;
        }

        // ---- squash ----
        {
            float zs[8];
#pragma unroll
            for (int k = 0; k < 8; k++) zs[k] = z[k] * z[k];
#pragma unroll
            for (int off = 16; off; off >>= 1)
#pragma unroll
                for (int k = 0; k < 8; k++)
                    zs[k] += __shfl_xor_sync(0xffffffffu, zs[k], off);
            if (lane == 0) {
#pragma unroll
                for (int k = 0; k < 8; k++) sm_red[k * 8 + warp] = zs[k];
            }
        }
        __syncthreads();
        if (tid < 8) {
            float sq = 0.f;
#pragma unroll
            for (int w = 0; w < 8; w++) sq += sm_red[tid * 8 + w];
            sm_sc[tid] = sq / (1.f + sq) / sqrtf(sq + 1e-8f);
        }
        __syncthreads();

        // ---- capsules -> SMEM + out ----
#pragma unroll
        for (int k = 0; k < 8; k++) {
            float c = sm_sc[k] * z[k];
            sm_caps[k * DIM + tid] = c;
            out[((size_t)b * NCAPS + k) * DIM + tid] = c;
        }
        __syncthreads();

        // ---- delta: stage-ordered, reissue stage for next batch ----
        {
            int kbase = (warp >> 2) * 4;
            int lphase = warp & 3;

            ull c2[4][4];
#pragma unroll
            for (int k = 0; k < 4; k++) {
                ulonglong2 ca = *(const ulonglong2*)&sm_caps[(kbase + k) * DIM + lane * 8];
                ulonglong2 cv = *(const ulonglong2*)&sm_caps[(kbase + k) * DIM + lane * 8 + 4];
                c2[k][0] = ca.x; c2[k][1] = ca.y; c2[k][2] = cv.x; c2[k][3] = cv.y;
            }

            bool writer = (lane & 7) == 0;
            int kw = kbase + ((lane >> 4) & 1) * 2 + ((lane >> 3) & 1);
            int bn = b + PGRID;
            const float* mbn = g_mapped + (size_t)bn * (SEQL * DIM);

            for (int s = 0; s < FR_NST; s++) {
                mbar_wait(sbase + s * 8, par);   // idempotent for s < nblkZ
                const float* st = ring + s * 4096;
                int base = s * 16;
                int rcnt = SEQL - base; if (rcnt > 16) rcnt = 16;
#pragma unroll
                for (int r0 = 0; r0 < 16; r0 += 4) {
                    int r = r0 + lphase;
                    if (r >= rcnt) break;
                    ulonglong2 m0 = *(const ulonglong2*)&st[r * 256 + lane * 8];
                    ulonglong2 m1 = *(const ulonglong2*)&st[r * 256 + lane * 8 + 4];
                    float p[4];
#pragma unroll
                    for (int k = 0; k < 4; k++) {
                        ull acc = 0ULL;
                        acc = ffma2(c2[k][0], m0.x, acc);
                        acc = ffma2(c2[k][1], m0.y, acc);
                        acc = ffma2(c2[k][2], m1.x, acc);
                        acc = ffma2(c2[k][3], m1.y, acc);
                        float2 f = unpack2(acc);
                        p[k] = f.x + f.y;
                    }
                    bool hi4 = (lane & 16) != 0;
                    float t0 = hi4 ? p[0] : p[2];
                    float t1 = hi4 ? p[1] : p[3];
                    t0 = __shfl_xor_sync(0xffffffffu, t0, 16);
                    t1 = __shfl_xor_sync(0xffffffffu, t1, 16);
                    float q0 = (hi4 ? p[2] : p[0]) + t0;
                    float q1 = (hi4 ? p[3] : p[1]) + t1;
                    bool hi3 = (lane & 8) != 0;
                    float t = hi3 ? q0 : q1;
                    t = __shfl_xor_sync(0xffffffffu, t, 8);
                    float rr = (hi3 ? q1 : q0) + t;
                    rr += __shfl_xor_sync(0xffffffffu, rr, 4);
                    rr += __shfl_xor_sync(0xffffffffu, rr, 2);
                    rr += __shfl_xor_sync(0xffffffffu, rr, 1);
                    if (writer)
                        g_part[((size_t)kw * SEQL + base + r) * NBATCH + b] = rr;
                }
                __syncthreads();   // stage fully consumed
                if (tid == 0 && bn < NBATCH) {
                    int rows2 = SEQL - s * 16; if (rows2 > 16) rows2 = 16;
                    uint32_t bytes = (uint32_t)rows2 * 1024u;
                    mbar_expect_tx(sbase + s * 8, bytes);
                    tma_1d(sbase + FR_RING + s * 16384,
                           mbn + (size_t)s * 16 * 256, bytes, sbase + s * 8);
                }
            }
        }
    }
}

// ---------------- k_caps: final capsules (R8 proven: 4x16KB ring) ---------
#define CAPS_SM_BYTES 72448

__global__ __launch_bounds__(256, 3) void k_caps(const int* __restrict__ seq_len,
                                                 float* __restrict__ out) {
    extern __shared__ __align__(16) char dsm[];
    uint32_t sbase = smem_u32(dsm);
    float* ring   = (float*)(dsm + 128);
    float* sm_w   = (float*)(dsm + 65664);
    float* sm_red = (float*)(dsm + 72064);
    float* sm_sc  = (float*)(dsm + 72320);

    int b = blockIdx.x;
    int tid = threadIdx.x;
    int warp = tid >> 5, lane = tid & 31;
    int seq = seq_len[b];
    int nblk = (seq + 15) >> 4;
    const float* __restrict__ mbp = g_mapped + (size_t)b * (SEQL * DIM);

    if (tid == 0) {
#pragma unroll
        for (int s = 0; s < 4; s++) mbar_init(sbase + s * 8, 1u);
    }
    __syncthreads();
    if (tid == 0) {
        int pre = nblk < 3 ? nblk : 3;
        for (int s = 0; s < pre; s++) {
            int rows = seq - s * 16; if (rows > 16) rows = 16;
            uint32_t bytes = (uint32_t)rows * 1024u;
            mbar_expect_tx(sbase + s * 8, bytes);
            tma_1d(sbase + 128 + s * 16384, mbp + (size_t)s * 16 * 256, bytes,
                   sbase + s * 8);
        }
    }

    {
        int k = warp;
        float vals[7];
        float mx = -INFINITY;
#pragma unroll
        for (int j = 0; j < 7; j++) {
            int l = lane + 32 * j;
            float v = (l < seq) ? g_logits[k * SEQL + l] : -INFINITY;
            vals[j] = v;
            mx = fmaxf(mx, v);
        }
#pragma unroll
        for (int off = 16; off; off >>= 1)
            mx = fmaxf(mx, __shfl_xor_sync(0xffffffffu, mx, off));
        float s = 0.f;
#pragma unroll
        for (int j = 0; j < 7; j++) {
            float e = expf(vals[j] - mx);
            vals[j] = e;
            s += e;
        }
#pragma unroll
        for (int off = 16; off; off >>= 1)
            s += __shfl_xor_sync(0xffffffffu, s, off);
        float inv = 1.f / s;
#pragma unroll
        for (int j = 0; j < 7; j++) {
            int l = lane + 32 * j;
            if (l < SEQL) sm_w[l * NCAPS + k] = vals[j] * inv;
        }
    }
    __syncthreads();

    ull z2[4] = {0ULL, 0ULL, 0ULL, 0ULL};
    for (int blk = 0; blk < nblk; blk++) {
        mbar_wait(sbase + (blk & 3) * 8, (uint32_t)((blk >> 2) & 1));
        const float* st = ring + (blk & 3) * 4096;
        int base = blk * 16;
        int rows = seq - base; if (rows > 16) rows = 16;
        if (rows == 16) {
#pragma unroll
            for (int r = 0; r < 16; r++) {
                ull md = dup2(st[r * 256 + tid]);
                ulonglong2 wa = *(const ulonglong2*)&sm_w[(base + r) * NCAPS];
                ulonglong2 wb = *(const ulonglong2*)&sm_w[(base + r) * NCAPS + 4];
                z2[0] = ffma2(md, wa.x, z2[0]);
                z2[1] = ffma2(md, wa.y, z2[1]);
                z2[2] = ffma2(md, wb.x, z2[2]);
                z2[3] = ffma2(md, wb.y, z2[3]);
            }
        } else {
            for (int r = 0; r < rows; r++) {
                ull md = dup2(st[r * 256 + tid]);
                ulonglong2 wa = *(const ulonglong2*)&sm_w[(base + r) * NCAPS];
                ulonglong2 wb = *(const ulonglong2*)&sm_w[(base + r) * NCAPS + 4];
                z2[0] = ffma2(md, wa.x, z2[0]);
                z2[1] = ffma2(md, wa.y, z2[1]);
                z2[2] = ffma2(md, wb.x, z2[2]);
                z2[3] = ffma2(md, wb.y, z2[3]);
            }
        }
        __syncthreads();
        int nb = blk + 3;
        if (tid == 0 && nb < nblk) {
            int rows2 = seq - nb * 16; if (rows2 > 16) rows2 = 16;
            uint32_t bytes = (uint32_t)rows2 * 1024u;
            mbar_expect_tx(sbase + (nb & 3) * 8, bytes);
            tma_1d(sbase + 128 + (nb & 3) * 16384, mbp + (size_t)nb * 16 * 256,
                   bytes, sbase + (nb & 3) * 8);
        }
    }

    float z[8];
    {
        float2 f;
        f = unpack2(z2[0]); z[0] = f.x; z[1] = f.y;
        f = unpack2(z2[1]); z[2] = f.x; z[3] = f.y;
        f = unpack2(z2[2]); z[4] = f.x; z[5] = f.y;
        f = unpack2(z2[3]); z[6] = f.x; z[7] = f.y;
    }

    {
        float zs[8];
#pragma unroll
        for (int k = 0; k < 8; k++) zs[k] = z[k] * z[k];
#pragma unroll
        for (int off = 16; off; off >>= 1)
#pragma unroll
            for (int k = 0; k < 8; k++)
                zs[k] += __shfl_xor_sync(0xffffffffu, zs[k], off);
        if (lane == 0) {
#pragma unroll
            for (int k = 0; k < 8; k++) sm_red[k * 8 + warp] = zs[k];
        }
    }
    __syncthreads();
    if (tid < 8) {
        float sq = 0.f;
#pragma unroll
        for (int w = 0; w < 8; w++) sq += sm_red[tid * 8 + w];
        sm_sc[tid] = sq / (1.f + sq) / sqrtf(sq + 1e-8f);
    }
    __syncthreads();

#pragma unroll
    for (int k = 0; k < 8; k++)
        out[((size_t)b * NCAPS + k) * DIM + tid] = sm_sc[k] * z[k];
}

// ---------------- deterministic batch-reduce of delta into logits --------
__global__ __launch_bounds__(256) void k_update() {
    __shared__ float red[256];
    int i = blockIdx.x;  // 0..1599
    const float4* row = (const float4*)(g_part + (size_t)i * NBATCH);
    float4 v = row[threadIdx.x];
    red[threadIdx.x] = v.x + v.y + v.z + v.w;
    __syncthreads();
#pragma unroll
    for (int st = 128; st; st >>= 1) {
        if (threadIdx.x < st) red[threadIdx.x] += red[threadIdx.x + st];
        __syncthreads();
    }
    if (threadIdx.x == 0) g_logits[i] += red[0];
}

// ---------------- launch --------------------------------------------------
extern "C" void kernel_launch(void* const* d_in, const int* in_sizes, int n_in,
                              void* d_out, int out_size) {
    const float* emb  = (const float*)d_in[0];
    const int*   seq  = (const int*)d_in[1];
    const float* rlog = (const float*)d_in[2];
    const float* W    = (const float*)d_in[3];
    float* out = (float*)d_out;

    cudaFuncSetAttribute(k_gemm_tc, cudaFuncAttributeMaxDynamicSharedMemorySize,
                         GSM_BYTES);
    cudaFuncSetAttribute(k_fusedp, cudaFuncAttributeMaxDynamicSharedMemorySize,
                         FR_BYTES);
    cudaFuncSetAttribute(k_caps, cudaFuncAttributeMaxDynamicSharedMemorySize,
                         CAPS_SM_BYTES);

    k_init<<<(NCAPS * SEQL + 255) / 256, 256>>>(rlog);
    k_convW<<<DIM, DIM>>>(W);
    k_gemm_tc<<<(NBATCH * SEQL) / 128, 256, GSM_BYTES>>>(emb, W);

    for (int it = 0; it < 2; it++) {
        k_fusedp<<<PGRID, 256, FR_BYTES>>>(seq, out);
        k_update<<<NCAPS * SEQL, 256>>>();
    }
    k_caps<<<NBATCH, 256, CAPS_SM_BYTES>>>(seq, out);
}

// round 13
// speedup vs baseline: 1.3777x; 1.3777x over previous
#include <cuda_runtime.h>
#include <cuda_bf16.h>
#include <cuda_fp16.h>
#include <math.h>
#include <stdint.h>

typedef unsigned long long ull;

#define NBATCH 1024
#define SEQL   200
#define DIM    256
#define NCAPS  8

#if !defined(__CUDA_ARCH__) || defined(__CUDA_ARCH_FEAT_SM103_ALL) || \
    defined(__CUDA_ARCH_FEAT_SM100_ALL) || defined(__CUDA_ARCH_FEAT_SM101_ALL)
#define TC_OK 1
#else
#define TC_OK 0
#endif

// ---------------- device scratch (no allocations allowed) ----------------
__device__ __half g_mappedh[(size_t)NBATCH * SEQL * DIM]; // 104.9 MB fp16
__device__ float g_logits[NCAPS * SEQL];
__device__ float g_part[(size_t)NCAPS * SEQL * NBATCH];   // [k*L][b]
__device__ __nv_bfloat16 g_WhT[DIM * DIM];
__device__ __nv_bfloat16 g_WlT[DIM * DIM];

// ---------------- f32x2 helpers ------------------------------------------
__device__ __forceinline__ ull ffma2(ull a, ull b, ull c) {
    ull d;
    asm("fma.rn.f32x2 %0, %1, %2, %3;" : "=l"(d) : "l"(a), "l"(b), "l"(c));
    return d;
}
__device__ __forceinline__ ull dup2(float x) {
    ull d;
    asm("mov.b64 %0, {%1, %1};" : "=l"(d) : "f"(x));
    return d;
}
__device__ __forceinline__ ull packf2(float a, float b) {
    ull d;
    asm("mov.b64 %0, {%1, %2};" : "=l"(d) : "f"(a), "f"(b));
    return d;
}
__device__ __forceinline__ float2 unpack2(ull a) {
    float2 f;
    asm("mov.b64 {%0, %1}, %2;" : "=f"(f.x), "=f"(f.y) : "l"(a));
    return f;
}

// ---------------- smem/mbarrier/TMA helpers (baseline PTX) ----------------
__device__ __forceinline__ uint32_t smem_u32(const void* p) {
    uint32_t a;
    asm("{ .reg .u64 t; cvta.to.shared.u64 t, %1; cvt.u32.u64 %0, t; }"
        : "=r"(a) : "l"(p));
    return a;
}
__device__ __forceinline__ void mbar_init(uint32_t a, uint32_t cnt) {
    asm volatile("mbarrier.init.shared.b64 [%0], %1;" :: "r"(a), "r"(cnt) : "memory");
}
__device__ __forceinline__ void mbar_expect_tx(uint32_t a, uint32_t bytes) {
    asm volatile("mbarrier.arrive.expect_tx.shared.b64 _, [%0], %1;"
                 :: "r"(a), "r"(bytes) : "memory");
}
__device__ __forceinline__ void tma_1d(uint32_t dst, const void* src,
                                       uint32_t bytes, uint32_t mbar) {
    asm volatile(
        "cp.async.bulk.shared::cluster.global.mbarrier::complete_tx::bytes "
        "[%0], [%1], %2, [%3];"
        :: "r"(dst), "l"(src), "r"(bytes), "r"(mbar) : "memory");
}
__device__ __forceinline__ void mbar_wait(uint32_t a, uint32_t par) {
    asm volatile(
        "{\n\t.reg .pred P;\n"
        "W%=:\n\t"
        "mbarrier.try_wait.parity.acquire.cta.shared::cta.b64 P, [%0], %1, 0x989680;\n\t"
        "@P bra D%=;\n\t"
        "bra W%=;\n"
        "D%=:\n\t}" :: "r"(a), "r"(par) : "memory");
}

#if TC_OK
__device__ __forceinline__ uint32_t elect1() {
    uint32_t p;
    asm volatile("{ .reg .pred p; elect.sync _|p, 0xFFFFFFFF; selp.b32 %0,1,0,p; }"
                 : "=r"(p));
    return p;
}
__device__ __forceinline__ void mma_f16_ss(uint32_t d, uint64_t a, uint64_t b,
                                           uint32_t id, uint32_t en) {
    asm volatile(
        "{\n\t.reg .pred p;\n\tsetp.ne.u32 p, %5, 0;\n\t"
        "tcgen05.mma.cta_group::1.kind::f16 [%0], %1, %2, %3, {%4,%4,%4,%4}, p;\n\t}"
        :: "r"(d), "l"(a), "l"(b), "r"(id), "r"(0u), "r"(en) : "memory");
}
#define LDTM_X32(r, addr) \
    asm volatile( \
        "tcgen05.ld.sync.aligned.32x32b.x32.b32 " \
        "{%0,%1,%2,%3,%4,%5,%6,%7,%8,%9,%10,%11,%12,%13,%14,%15," \
        "%16,%17,%18,%19,%20,%21,%22,%23,%24,%25,%26,%27,%28,%29,%30,%31}, [%32];" \
        : "=r"((r)[0]),"=r"((r)[1]),"=r"((r)[2]),"=r"((r)[3]), \
          "=r"((r)[4]),"=r"((r)[5]),"=r"((r)[6]),"=r"((r)[7]), \
          "=r"((r)[8]),"=r"((r)[9]),"=r"((r)[10]),"=r"((r)[11]), \
          "=r"((r)[12]),"=r"((r)[13]),"=r"((r)[14]),"=r"((r)[15]), \
          "=r"((r)[16]),"=r"((r)[17]),"=r"((r)[18]),"=r"((r)[19]), \
          "=r"((r)[20]),"=r"((r)[21]),"=r"((r)[22]),"=r"((r)[23]), \
          "=r"((r)[24]),"=r"((r)[25]),"=r"((r)[26]),"=r"((r)[27]), \
          "=r"((r)[28]),"=r"((r)[29]),"=r"((r)[30]),"=r"((r)[31]) \
        : "r"(addr))
#endif  // TC_OK

// ---------------- init kernels -------------------------------------------
__global__ void k_init(const float* __restrict__ rlog) {
    int i = blockIdx.x * blockDim.x + threadIdx.x;
    if (i < NCAPS * SEQL) g_logits[i] = rlog[i];
}

__global__ void k_convW(const float* __restrict__ W) {
    int k = blockIdx.x;
    int n = threadIdx.x;
    float v = W[k * DIM + n];
    __nv_bfloat16 h = __float2bfloat16(v);
    float r = v - __bfloat162float(h);
    g_WhT[n * DIM + k] = h;
    g_WlT[n * DIM + k] = __float2bfloat16(r);
}

// ---------------- tensor-core GEMM: g_mappedh = fp16(A @ W) ---------------
#define OFF_AH 1024
#define OFF_AL 17408
#define OFF_BH 33792
#define OFF_BL 66560
#define GSM_BYTES 99328

__global__ __launch_bounds__(256, 2) void k_gemm_tc(const float* __restrict__ A,
                                                    const float* __restrict__ W) {
#if TC_OK
    extern __shared__ __align__(16) float sm[];
    char* sb = (char*)sm;
    uint32_t sbase = smem_u32(sm);
    int tid = threadIdx.x, wid = tid >> 5;
    size_t m0 = (size_t)blockIdx.x * 128;

    if (wid == 0) {
        asm volatile("tcgen05.alloc.cta_group::1.sync.aligned.shared::cta.b32 [%0], %1;"
                     :: "r"(sbase), "r"(256u) : "memory");
        asm volatile("tcgen05.relinquish_alloc_permit.cta_group::1.sync.aligned;");
    }
    __syncthreads();
    uint32_t tb;
    asm volatile("ld.shared.b32 %0, [%1];" : "=r"(tb) : "r"(sbase));

    if (tid == 0) mbar_init(sbase + 8, 1u);
    __syncthreads();

    const uint64_t DB = (2ULL << 61) | (1ULL << 46) | (64ULL << 32) | (1ULL << 16);
    uint64_t dAh = DB | (((uint64_t)(sbase + OFF_AH) >> 4) & 0x3FFF);
    uint64_t dAl = DB | (((uint64_t)(sbase + OFF_AL) >> 4) & 0x3FFF);
    uint64_t dBh = DB | (((uint64_t)(sbase + OFF_BH) >> 4) & 0x3FFF);
    uint64_t dBl = DB | (((uint64_t)(sbase + OFF_BL) >> 4) & 0x3FFF);
    const uint32_t idesc = (1u << 4) | (1u << 7) | (1u << 10) |
                           ((DIM / 8) << 17) | ((128 / 16) << 24);

    float4 fA[8];
#pragma unroll
    for (int i = 0; i < 8; i++) {
        int idx = tid + i * 256;
        int r = idx >> 4, c4 = idx & 15;
        fA[i] = *(const float4*)(A + (m0 + r) * DIM + 0 + c4 * 4);
    }

    uint32_t first = 0;
    for (int c = 0; c < 4; c++) {
        int k0 = c * 64;
#pragma unroll
        for (int i = 0; i < 8; i++) {
            int idx = tid + i * 256;
            int r = idx >> 4, c4 = idx & 15;
            float4 f = fA[i];
            __nv_bfloat16 h0 = __float2bfloat16(f.x), h1 = __float2bfloat16(f.y),
                          h2 = __float2bfloat16(f.z), h3 = __float2bfloat16(f.w);
            float l0 = f.x - __bfloat162float(h0), l1 = f.y - __bfloat162float(h1),
                  l2 = f.z - __bfloat162float(h2), l3 = f.w - __bfloat162float(h3);
            uint32_t off = r * 128 + c4 * 8;
            uint32_t sw = off ^ ((off >> 3) & 0x70);
            uint2 uh, ulv;
            uh.x = ((uint32_t)__bfloat16_as_ushort(h1) << 16) | __bfloat16_as_ushort(h0);
            uh.y = ((uint32_t)__bfloat16_as_ushort(h3) << 16) | __bfloat16_as_ushort(h2);
            __nv_bfloat16 q0 = __float2bfloat16(l0), q1 = __float2bfloat16(l1),
                          q2 = __float2bfloat16(l2), q3 = __float2bfloat16(l3);
            ulv.x = ((uint32_t)__bfloat16_as_ushort(q1) << 16) | __bfloat16_as_ushort(q0);
            ulv.y = ((uint32_t)__bfloat16_as_ushort(q3) << 16) | __bfloat16_as_ushort(q2);
            *(uint2*)(sb + OFF_AH + sw) = uh;
            *(uint2*)(sb + OFF_AL + sw) = ulv;
        }
#pragma unroll
        for (int i = 0; i < 8; i++) {
            int idx = tid + i * 256;
            int r = idx >> 3, cc = idx & 7;
            uint32_t off = r * 128 + cc * 16;
            uint32_t sw = off ^ ((off >> 3) & 0x70);
            uint4 vh = *(const uint4*)((const char*)g_WhT + r * 512 + k0 * 2 + cc * 16);
            uint4 vl = *(const uint4*)((const char*)g_WlT + r * 512 + k0 * 2 + cc * 16);
            *(uint4*)(sb + OFF_BH + sw) = vh;
            *(uint4*)(sb + OFF_BL + sw) = vl;
        }
        __syncthreads();
        if (wid == 0) {
            asm volatile("fence.proxy.async.shared::cta;" ::: "memory");
            if (elect1()) {
#pragma unroll
                for (int s = 0; s < 4; s++) {
                    mma_f16_ss(tb, dAh + s * 2, dBh + s * 2, idesc, first);
                    first = 1;
                    mma_f16_ss(tb, dAh + s * 2, dBl + s * 2, idesc, 1);
                    mma_f16_ss(tb, dAl + s * 2, dBh + s * 2, idesc, 1);
                }
                asm volatile(
                    "tcgen05.commit.cta_group::1.mbarrier::arrive::one.shared::cluster.b64 [%0];"
                    :: "r"(sbase + 8) : "memory");
            }
        }
        if (c < 3) {
            int kn = k0 + 64;
#pragma unroll
            for (int i = 0; i < 8; i++) {
                int idx = tid + i * 256;
                int r = idx >> 4, c4 = idx & 15;
                fA[i] = *(const float4*)(A + (m0 + r) * DIM + kn + c4 * 4);
            }
        }
        mbar_wait(sbase + 8, (uint32_t)(c & 1));
    }

    asm volatile("tcgen05.fence::after_thread_sync;" ::: "memory");
    if (tid < 128) {
        __half* Crow = g_mappedh + (m0 + tid) * DIM;
#pragma unroll
        for (int j = 0; j < 8; j++) {
            uint32_t r[32];
            LDTM_X32(r, tb + j * 32);
            asm volatile("tcgen05.wait::ld.sync.aligned;" ::: "memory");
            uint32_t h[16];
#pragma unroll
            for (int q = 0; q < 16; q++) {
                __half2 hv = __floats2half2_rn(__uint_as_float(r[2 * q]),
                                               __uint_as_float(r[2 * q + 1]));
                h[q] = *(uint32_t*)&hv;
            }
#pragma unroll
            for (int t = 0; t < 4; t++) {
                uint4 v = make_uint4(h[4 * t], h[4 * t + 1], h[4 * t + 2], h[4 * t + 3]);
                *(uint4*)(Crow + j * 32 + t * 8) = v;
            }
        }
    }
    __syncthreads();
    if (wid == 0) {
        asm volatile("tcgen05.dealloc.cta_group::1.sync.aligned.b32 %0, %1;"
                     :: "r"(tb), "r"(256u));
    }
#else
    size_t m0 = (size_t)blockIdx.x * 128;
    int tid = threadIdx.x;
    for (int e = tid; e < 128 * 256; e += 256) {
        int r = e >> 8, n = e & 255;
        float acc = 0.f;
        for (int k = 0; k < DIM; k++)
            acc += A[(m0 + r) * DIM + k] * W[k * DIM + n];
        g_mappedh[(m0 + r) * DIM + n] = __float2half(acc);
    }
#endif
}

// ---------------- k_caps: softmax + Z + squash, fp16 4x8KB TMA ring -------
// stage = 16 rows x 512 B. layout: mbars[0,32) | ring@128 (32768) |
// weights | red | sc
#define CR_RING 128
#define CR_W    (CR_RING + 4 * 8192)   // 32896
#define CR_RED  (CR_W + SEQL * NCAPS * 4)  // 39296
#define CR_SC   (CR_RED + 256)         // 39552
#define CAPS_SM_BYTES (CR_SC + 64)     // 39616

__global__ __launch_bounds__(256, 3) void k_caps(const int* __restrict__ seq_len,
                                                 float* __restrict__ out) {
    extern __shared__ __align__(16) char dsm[];
    uint32_t sbase = smem_u32(dsm);
    float* sm_w   = (float*)(dsm + CR_W);
    float* sm_red = (float*)(dsm + CR_RED);
    float* sm_sc  = (float*)(dsm + CR_SC);

    int b = blockIdx.x;
    int tid = threadIdx.x;
    int warp = tid >> 5, lane = tid & 31;
    int seq = seq_len[b];
    int nblk = (seq + 15) >> 4;
    const __half* __restrict__ mbp = g_mappedh + (size_t)b * (SEQL * DIM);

    if (tid == 0) {
#pragma unroll
        for (int s = 0; s < 4; s++) mbar_init(sbase + s * 8, 1u);
    }
    __syncthreads();
    if (tid == 0) {
        int pre = nblk < 3 ? nblk : 3;
        for (int s = 0; s < pre; s++) {
            int rows = seq - s * 16; if (rows > 16) rows = 16;
            uint32_t bytes = (uint32_t)rows * 512u;
            mbar_expect_tx(sbase + s * 8, bytes);
            tma_1d(sbase + CR_RING + s * 8192, mbp + (size_t)s * 16 * 256, bytes,
                   sbase + s * 8);
        }
    }

    // ---- masked softmax (overlaps TMA) ----
    {
        int k = warp;
        float vals[7];
        float mx = -INFINITY;
#pragma unroll
        for (int j = 0; j < 7; j++) {
            int l = lane + 32 * j;
            float v = (l < seq) ? g_logits[k * SEQL + l] : -INFINITY;
            vals[j] = v;
            mx = fmaxf(mx, v);
        }
#pragma unroll
        for (int off = 16; off; off >>= 1)
            mx = fmaxf(mx, __shfl_xor_sync(0xffffffffu, mx, off));
        float s = 0.f;
#pragma unroll
        for (int j = 0; j < 7; j++) {
            float e = expf(vals[j] - mx);
            vals[j] = e;
            s += e;
        }
#pragma unroll
        for (int off = 16; off; off >>= 1)
            s += __shfl_xor_sync(0xffffffffu, s, off);
        float inv = 1.f / s;
#pragma unroll
        for (int j = 0; j < 7; j++) {
            int l = lane + 32 * j;
            if (l < SEQL) sm_w[l * NCAPS + k] = vals[j] * inv;
        }
    }
    __syncthreads();

    // ---- Z from fp16 SMEM ring ----
    ull z2[4] = {0ULL, 0ULL, 0ULL, 0ULL};
    for (int blk = 0; blk < nblk; blk++) {
        mbar_wait(sbase + (blk & 3) * 8, (uint32_t)((blk >> 2) & 1));
        const __half* st = (const __half*)(dsm + CR_RING + (blk & 3) * 8192);
        int base = blk * 16;
        int rows = seq - base; if (rows > 16) rows = 16;
        if (rows == 16) {
#pragma unroll
            for (int r = 0; r < 16; r++) {
                ull md = dup2(__half2float(st[r * 256 + tid]));
                ulonglong2 wa = *(const ulonglong2*)&sm_w[(base + r) * NCAPS];
                ulonglong2 wb = *(const ulonglong2*)&sm_w[(base + r) * NCAPS + 4];
                z2[0] = ffma2(md, wa.x, z2[0]);
                z2[1] = ffma2(md, wa.y, z2[1]);
                z2[2] = ffma2(md, wb.x, z2[2]);
                z2[3] = ffma2(md, wb.y, z2[3]);
            }
        } else {
            for (int r = 0; r < rows; r++) {
                ull md = dup2(__half2float(st[r * 256 + tid]));
                ulonglong2 wa = *(const ulonglong2*)&sm_w[(base + r) * NCAPS];
                ulonglong2 wb = *(const ulonglong2*)&sm_w[(base + r) * NCAPS + 4];
                z2[0] = ffma2(md, wa.x, z2[0]);
                z2[1] = ffma2(md, wa.y, z2[1]);
                z2[2] = ffma2(md, wb.x, z2[2]);
                z2[3] = ffma2(md, wb.y, z2[3]);
            }
        }
        __syncthreads();
        int nb = blk + 3;
        if (tid == 0 && nb < nblk) {
            int rows2 = seq - nb * 16; if (rows2 > 16) rows2 = 16;
            uint32_t bytes = (uint32_t)rows2 * 512u;
            mbar_expect_tx(sbase + (nb & 3) * 8, bytes);
            tma_1d(sbase + CR_RING + (nb & 3) * 8192, mbp + (size_t)nb * 16 * 256,
                   bytes, sbase + (nb & 3) * 8);
        }
    }

    float z[8];
    {
        float2 f;
        f = unpack2(z2[0]); z[0] = f.x; z[1] = f.y;
        f = unpack2(z2[1]); z[2] = f.x; z[3] = f.y;
        f = unpack2(z2[2]); z[4] = f.x; z[5] = f.y;
        f = unpack2(z2[3]); z[6] = f.x; z[7] = f.y;
    }

    // ---- squash ----
    {
        float zs[8];
#pragma unroll
        for (int k = 0; k < 8; k++) zs[k] = z[k] * z[k];
#pragma unroll
        for (int off = 16; off; off >>= 1)
#pragma unroll
            for (int k = 0; k < 8; k++)
                zs[k] += __shfl_xor_sync(0xffffffffu, zs[k], off);
        if (lane == 0) {
#pragma unroll
            for (int k = 0; k < 8; k++) sm_red[k * 8 + warp] = zs[k];
        }
    }
    __syncthreads();
    if (tid < 8) {
        float sq = 0.f;
#pragma unroll
        for (int w = 0; w < 8; w++) sq += sm_red[tid * 8 + w];
        sm_sc[tid] = sq / (1.f + sq) / sqrtf(sq + 1e-8f);
    }
    __syncthreads();

#pragma unroll
    for (int k = 0; k < 8; k++)
        out[((size_t)b * NCAPS + k) * DIM + tid] = sm_sc[k] * z[k];
}

// ---------------- k_delta: fp16-stream delta partials ---------------------
#define DELTA_SM_BYTES (CR_RING + 4 * 8192)   // 32896
#define DNBLK 13

__global__ __launch_bounds__(256, 3) void k_delta(const float* __restrict__ caps) {
    extern __shared__ __align__(16) char dsm[];
    uint32_t sbase = smem_u32(dsm);

    int b = blockIdx.x;
    int tid = threadIdx.x;
    int warp = tid >> 5, lane = tid & 31;
    int kbase = (warp >> 2) * 4;
    int lphase = warp & 3;
    const __half* __restrict__ mbp = g_mappedh + (size_t)b * (SEQL * DIM);
    const float* __restrict__ cb = caps + (size_t)b * (NCAPS * DIM);

    if (tid == 0) {
#pragma unroll
        for (int s = 0; s < 4; s++) mbar_init(sbase + s * 8, 1u);
    }
    __syncthreads();
    if (tid == 0) {
        for (int s = 0; s < 3; s++) {
            int rows = SEQL - s * 16; if (rows > 16) rows = 16;
            uint32_t bytes = (uint32_t)rows * 512u;
            mbar_expect_tx(sbase + s * 8, bytes);
            tma_1d(sbase + CR_RING + s * 8192, mbp + (size_t)s * 16 * 256, bytes,
                   sbase + s * 8);
        }
    }

    // caps for 4 owned capsules as f32x2 pairs
    ull c2[4][4];
#pragma unroll
    for (int k = 0; k < 4; k++) {
        ulonglong2 ca = *(const ulonglong2*)&cb[(kbase + k) * DIM + lane * 8];
        ulonglong2 cv = *(const ulonglong2*)&cb[(kbase + k) * DIM + lane * 8 + 4];
        c2[k][0] = ca.x; c2[k][1] = ca.y; c2[k][2] = cv.x; c2[k][3] = cv.y;
    }

    bool writer = (lane & 7) == 0;
    int kw = kbase + ((lane >> 4) & 1) * 2 + ((lane >> 3) & 1);

    for (int blk = 0; blk < DNBLK; blk++) {
        mbar_wait(sbase + (blk & 3) * 8, (uint32_t)((blk >> 2) & 1));
        const __half* st = (const __half*)(dsm + CR_RING + (blk & 3) * 8192);
        int base = blk * 16;
        int rcnt = SEQL - base; if (rcnt > 16) rcnt = 16;
#pragma unroll
        for (int r0 = 0; r0 < 16; r0 += 4) {
            int r = r0 + lphase;
            if (r >= rcnt) break;
            // 8 halves for this thread's o-slice: one uint4
            uint4 hv = *(const uint4*)&st[r * 256 + lane * 8];
            const __half2* hp = (const __half2*)&hv;
            float2 f0 = __half22float2(hp[0]);
            float2 f1 = __half22float2(hp[1]);
            float2 f2 = __half22float2(hp[2]);
            float2 f3 = __half22float2(hp[3]);
            ull m0x = packf2(f0.x, f0.y);
            ull m0y = packf2(f1.x, f1.y);
            ull m1x = packf2(f2.x, f2.y);
            ull m1y = packf2(f3.x, f3.y);
            float p[4];
#pragma unroll
            for (int k = 0; k < 4; k++) {
                ull acc = 0ULL;
                acc = ffma2(c2[k][0], m0x, acc);
                acc = ffma2(c2[k][1], m0y, acc);
                acc = ffma2(c2[k][2], m1x, acc);
                acc = ffma2(c2[k][3], m1y, acc);
                float2 f = unpack2(acc);
                p[k] = f.x + f.y;
            }
            bool hi4 = (lane & 16) != 0;
            float t0 = hi4 ? p[0] : p[2];
            float t1 = hi4 ? p[1] : p[3];
            t0 = __shfl_xor_sync(0xffffffffu, t0, 16);
            t1 = __shfl_xor_sync(0xffffffffu, t1, 16);
            float q0 = (hi4 ? p[2] : p[0]) + t0;
            float q1 = (hi4 ? p[3] : p[1]) + t1;
            bool hi3 = (lane & 8) != 0;
            float t = hi3 ? q0 : q1;
            t = __shfl_xor_sync(0xffffffffu, t, 8);
            float rr = (hi3 ? q1 : q0) + t;
            rr += __shfl_xor_sync(0xffffffffu, rr, 4);
            rr += __shfl_xor_sync(0xffffffffu, rr, 2);
            rr += __shfl_xor_sync(0xffffffffu, rr, 1);
            if (writer)
                g_part[((size_t)kw * SEQL + base + r) * NBATCH + b] = rr;
        }
        __syncthreads();
        int nb = blk + 3;
        if (tid == 0 && nb < DNBLK) {
            int rows2 = SEQL - nb * 16; if (rows2 > 16) rows2 = 16;
            uint32_t bytes = (uint32_t)rows2 * 512u;
            mbar_expect_tx(sbase + (nb & 3) * 8, bytes);
            tma_1d(sbase + CR_RING + (nb & 3) * 8192, mbp + (size_t)nb * 16 * 256,
                   bytes, sbase + (nb & 3) * 8);
        }
    }
}

// ---------------- deterministic batch-reduce of delta into logits --------
__global__ __launch_bounds__(256) void k_update() {
    __shared__ float red[256];
    int i = blockIdx.x;  // 0..1599
    const float4* row = (const float4*)(g_part + (size_t)i * NBATCH);
    float4 v = row[threadIdx.x];
    red[threadIdx.x] = v.x + v.y + v.z + v.w;
    __syncthreads();
#pragma unroll
    for (int st = 128; st; st >>= 1) {
        if (threadIdx.x < st) red[threadIdx.x] += red[threadIdx.x + st];
        __syncthreads();
    }
    if (threadIdx.x == 0) g_logits[i] += red[0];
}

// ---------------- launch --------------------------------------------------
extern "C" void kernel_launch(void* const* d_in, const int* in_sizes, int n_in,
                              void* d_out, int out_size) {
    const float* emb  = (const float*)d_in[0];
    const int*   seq  = (const int*)d_in[1];
    const float* rlog = (const float*)d_in[2];
    const float* W    = (const float*)d_in[3];
    float* out = (float*)d_out;

    cudaFuncSetAttribute(k_gemm_tc, cudaFuncAttributeMaxDynamicSharedMemorySize,
                         GSM_BYTES);

    k_init<<<(NCAPS * SEQL + 255) / 256, 256>>>(rlog);
    k_convW<<<DIM, DIM>>>(W);
    k_gemm_tc<<<(NBATCH * SEQL) / 128, 256, GSM_BYTES>>>(emb, W);

    for (int it = 0; it < 3; it++) {
        k_caps<<<NBATCH, 256, CAPS_SM_BYTES>>>(seq, out);
        if (it < 2) {
            k_delta<<<NBATCH, 256, DELTA_SM_BYTES>>>(out);
            k_update<<<NCAPS * SEQL, 256>>>();
        }
    }
}

// round 15
// speedup vs baseline: 1.4482x; 1.0511x over previous
#include <cuda_runtime.h>
#include <cuda_bf16.h>
#include <cuda_fp16.h>
#include <math.h>
#include <stdint.h>

typedef unsigned long long ull;

#define NBATCH 1024
#define SEQL   200
#define DIM    256
#define NCAPS  8

#if !defined(__CUDA_ARCH__) || defined(__CUDA_ARCH_FEAT_SM103_ALL) || \
    defined(__CUDA_ARCH_FEAT_SM100_ALL) || defined(__CUDA_ARCH_FEAT_SM101_ALL)
#define TC_OK 1
#else
#define TC_OK 0
#endif

// ---------------- device scratch (no allocations allowed) ----------------
__device__ __half g_mappedh[(size_t)NBATCH * SEQL * DIM]; // 104.9 MB fp16
__device__ float g_logits[NCAPS * SEQL];
__device__ float g_part[(size_t)NCAPS * SEQL * NBATCH];   // [k*L][b]
__device__ __nv_bfloat16 g_WhT[DIM * DIM];
__device__ __nv_bfloat16 g_WlT[DIM * DIM];

// ---------------- f32x2 helpers ------------------------------------------
__device__ __forceinline__ ull ffma2(ull a, ull b, ull c) {
    ull d;
    asm("fma.rn.f32x2 %0, %1, %2, %3;" : "=l"(d) : "l"(a), "l"(b), "l"(c));
    return d;
}
__device__ __forceinline__ ull dup2(float x) {
    ull d;
    asm("mov.b64 %0, {%1, %1};" : "=l"(d) : "f"(x));
    return d;
}
__device__ __forceinline__ ull packf2(float a, float b) {
    ull d;
    asm("mov.b64 %0, {%1, %2};" : "=l"(d) : "f"(a), "f"(b));
    return d;
}
__device__ __forceinline__ float2 unpack2(ull a) {
    float2 f;
    asm("mov.b64 {%0, %1}, %2;" : "=f"(f.x), "=f"(f.y) : "l"(a));
    return f;
}

// ---------------- smem/mbarrier/TMA helpers (baseline PTX) ----------------
__device__ __forceinline__ uint32_t smem_u32(const void* p) {
    uint32_t a;
    asm("{ .reg .u64 t; cvta.to.shared.u64 t, %1; cvt.u32.u64 %0, t; }"
        : "=r"(a) : "l"(p));
    return a;
}
__device__ __forceinline__ void mbar_init(uint32_t a, uint32_t cnt) {
    asm volatile("mbarrier.init.shared.b64 [%0], %1;" :: "r"(a), "r"(cnt) : "memory");
}
__device__ __forceinline__ void mbar_expect_tx(uint32_t a, uint32_t bytes) {
    asm volatile("mbarrier.arrive.expect_tx.shared.b64 _, [%0], %1;"
                 :: "r"(a), "r"(bytes) : "memory");
}
__device__ __forceinline__ void tma_1d(uint32_t dst, const void* src,
                                       uint32_t bytes, uint32_t mbar) {
    asm volatile(
        "cp.async.bulk.shared::cluster.global.mbarrier::complete_tx::bytes "
        "[%0], [%1], %2, [%3];"
        :: "r"(dst), "l"(src), "r"(bytes), "r"(mbar) : "memory");
}
__device__ __forceinline__ void mbar_wait(uint32_t a, uint32_t par) {
    asm volatile(
        "{\n\t.reg .pred P;\n"
        "W%=:\n\t"
        "mbarrier.try_wait.parity.acquire.cta.shared::cta.b64 P, [%0], %1, 0x989680;\n\t"
        "@P bra D%=;\n\t"
        "bra W%=;\n"
        "D%=:\n\t}" :: "r"(a), "r"(par) : "memory");
}

#if TC_OK
__device__ __forceinline__ uint32_t elect1() {
    uint32_t p;
    asm volatile("{ .reg .pred p; elect.sync _|p, 0xFFFFFFFF; selp.b32 %0,1,0,p; }"
                 : "=r"(p));
    return p;
}
__device__ __forceinline__ void mma_f16_ss(uint32_t d, uint64_t a, uint64_t b,
                                           uint32_t id, uint32_t en) {
    asm volatile(
        "{\n\t.reg .pred p;\n\tsetp.ne.u32 p, %5, 0;\n\t"
        "tcgen05.mma.cta_group::1.kind::f16 [%0], %1, %2, %3, {%4,%4,%4,%4}, p;\n\t}"
        :: "r"(d), "l"(a), "l"(b), "r"(id), "r"(0u), "r"(en) : "memory");
}
#define LDTM_X32(r, addr) \
    asm volatile( \
        "tcgen05.ld.sync.aligned.32x32b.x32.b32 " \
        "{%0,%1,%2,%3,%4,%5,%6,%7,%8,%9,%10,%11,%12,%13,%14,%15," \
        "%16,%17,%18,%19,%20,%21,%22,%23,%24,%25,%26,%27,%28,%29,%30,%31}, [%32];" \
        : "=r"((r)[0]),"=r"((r)[1]),"=r"((r)[2]),"=r"((r)[3]), \
          "=r"((r)[4]),"=r"((r)[5]),"=r"((r)[6]),"=r"((r)[7]), \
          "=r"((r)[8]),"=r"((r)[9]),"=r"((r)[10]),"=r"((r)[11]), \
          "=r"((r)[12]),"=r"((r)[13]),"=r"((r)[14]),"=r"((r)[15]), \
          "=r"((r)[16]),"=r"((r)[17]),"=r"((r)[18]),"=r"((r)[19]), \
          "=r"((r)[20]),"=r"((r)[21]),"=r"((r)[22]),"=r"((r)[23]), \
          "=r"((r)[24]),"=r"((r)[25]),"=r"((r)[26]),"=r"((r)[27]), \
          "=r"((r)[28]),"=r"((r)[29]),"=r"((r)[30]),"=r"((r)[31]) \
        : "r"(addr))
#endif  // TC_OK

// ---------------- init kernels -------------------------------------------
__global__ void k_init(const float* __restrict__ rlog) {
    int i = blockIdx.x * blockDim.x + threadIdx.x;
    if (i < NCAPS * SEQL) g_logits[i] = rlog[i];
}

__global__ void k_convW(const float* __restrict__ W) {
    int k = blockIdx.x;
    int n = threadIdx.x;
    float v = W[k * DIM + n];
    __nv_bfloat16 h = __float2bfloat16(v);
    float r = v - __bfloat162float(h);
    g_WhT[n * DIM + k] = h;
    g_WlT[n * DIM + k] = __float2bfloat16(r);
}

// ---------------- tensor-core GEMM: g_mappedh = fp16(A @ W) ---------------
#define OFF_AH 1024
#define OFF_AL 17408
#define OFF_BH 33792
#define OFF_BL 66560
#define GSM_BYTES 99328

__global__ __launch_bounds__(256, 2) void k_gemm_tc(const float* __restrict__ A,
                                                    const float* __restrict__ W) {
#if TC_OK
    extern __shared__ __align__(16) float sm[];
    char* sb = (char*)sm;
    uint32_t sbase = smem_u32(sm);
    int tid = threadIdx.x, wid = tid >> 5;
    size_t m0 = (size_t)blockIdx.x * 128;

    if (wid == 0) {
        asm volatile("tcgen05.alloc.cta_group::1.sync.aligned.shared::cta.b32 [%0], %1;"
                     :: "r"(sbase), "r"(256u) : "memory");
        asm volatile("tcgen05.relinquish_alloc_permit.cta_group::1.sync.aligned;");
    }
    __syncthreads();
    uint32_t tb;
    asm volatile("ld.shared.b32 %0, [%1];" : "=r"(tb) : "r"(sbase));

    if (tid == 0) mbar_init(sbase + 8, 1u);
    __syncthreads();

    const uint64_t DB = (2ULL << 61) | (1ULL << 46) | (64ULL << 32) | (1ULL << 16);
    uint64_t dAh = DB | (((uint64_t)(sbase + OFF_AH) >> 4) & 0x3FFF);
    uint64_t dAl = DB | (((uint64_t)(sbase + OFF_AL) >> 4) & 0x3FFF);
    uint64_t dBh = DB | (((uint64_t)(sbase + OFF_BH) >> 4) & 0x3FFF);
    uint64_t dBl = DB | (((uint64_t)(sbase + OFF_BL) >> 4) & 0x3FFF);
    const uint32_t idesc = (1u << 4) | (1u << 7) | (1u << 10) |
                           ((DIM / 8) << 17) | ((128 / 16) << 24);

    float4 fA[8];
#pragma unroll
    for (int i = 0; i < 8; i++) {
        int idx = tid + i * 256;
        int r = idx >> 4, c4 = idx & 15;
        fA[i] = *(const float4*)(A + (m0 + r) * DIM + 0 + c4 * 4);
    }

    uint32_t first = 0;
    for (int c = 0; c < 4; c++) {
        int k0 = c * 64;
#pragma unroll
        for (int i = 0; i < 8; i++) {
            int idx = tid + i * 256;
            int r = idx >> 4, c4 = idx & 15;
            float4 f = fA[i];
            __nv_bfloat16 h0 = __float2bfloat16(f.x), h1 = __float2bfloat16(f.y),
                          h2 = __float2bfloat16(f.z), h3 = __float2bfloat16(f.w);
            float l0 = f.x - __bfloat162float(h0), l1 = f.y - __bfloat162float(h1),
                  l2 = f.z - __bfloat162float(h2), l3 = f.w - __bfloat162float(h3);
            uint32_t off = r * 128 + c4 * 8;
            uint32_t sw = off ^ ((off >> 3) & 0x70);
            uint2 uh, ulv;
            uh.x = ((uint32_t)__bfloat16_as_ushort(h1) << 16) | __bfloat16_as_ushort(h0);
            uh.y = ((uint32_t)__bfloat16_as_ushort(h3) << 16) | __bfloat16_as_ushort(h2);
            __nv_bfloat16 q0 = __float2bfloat16(l0), q1 = __float2bfloat16(l1),
                          q2 = __float2bfloat16(l2), q3 = __float2bfloat16(l3);
            ulv.x = ((uint32_t)__bfloat16_as_ushort(q1) << 16) | __bfloat16_as_ushort(q0);
            ulv.y = ((uint32_t)__bfloat16_as_ushort(q3) << 16) | __bfloat16_as_ushort(q2);
            *(uint2*)(sb + OFF_AH + sw) = uh;
            *(uint2*)(sb + OFF_AL + sw) = ulv;
        }
#pragma unroll
        for (int i = 0; i < 8; i++) {
            int idx = tid + i * 256;
            int r = idx >> 3, cc = idx & 7;
            uint32_t off = r * 128 + cc * 16;
            uint32_t sw = off ^ ((off >> 3) & 0x70);
            uint4 vh = *(const uint4*)((const char*)g_WhT + r * 512 + k0 * 2 + cc * 16);
            uint4 vl = *(const uint4*)((const char*)g_WlT + r * 512 + k0 * 2 + cc * 16);
            *(uint4*)(sb + OFF_BH + sw) = vh;
            *(uint4*)(sb + OFF_BL + sw) = vl;
        }
        __syncthreads();
        if (wid == 0) {
            asm volatile("fence.proxy.async.shared::cta;" ::: "memory");
            if (elect1()) {
#pragma unroll
                for (int s = 0; s < 4; s++) {
                    mma_f16_ss(tb, dAh + s * 2, dBh + s * 2, idesc, first);
                    first = 1;
                    mma_f16_ss(tb, dAh + s * 2, dBl + s * 2, idesc, 1);
                    mma_f16_ss(tb, dAl + s * 2, dBh + s * 2, idesc, 1);
                }
                asm volatile(
                    "tcgen05.commit.cta_group::1.mbarrier::arrive::one.shared::cluster.b64 [%0];"
                    :: "r"(sbase + 8) : "memory");
            }
        }
        if (c < 3) {
            int kn = k0 + 64;
#pragma unroll
            for (int i = 0; i < 8; i++) {
                int idx = tid + i * 256;
                int r = idx >> 4, c4 = idx & 15;
                fA[i] = *(const float4*)(A + (m0 + r) * DIM + kn + c4 * 4);
            }
        }
        mbar_wait(sbase + 8, (uint32_t)(c & 1));
    }

    asm volatile("tcgen05.fence::after_thread_sync;" ::: "memory");
    if (tid < 128) {
        __half* Crow = g_mappedh + (m0 + tid) * DIM;
#pragma unroll
        for (int j = 0; j < 8; j++) {
            uint32_t r[32];
            LDTM_X32(r, tb + j * 32);
            asm volatile("tcgen05.wait::ld.sync.aligned;" ::: "memory");
            uint32_t h[16];
#pragma unroll
            for (int q = 0; q < 16; q++) {
                __half2 hv = __floats2half2_rn(__uint_as_float(r[2 * q]),
                                               __uint_as_float(r[2 * q + 1]));
                h[q] = *(uint32_t*)&hv;
            }
#pragma unroll
            for (int t = 0; t < 4; t++) {
                uint4 v = make_uint4(h[4 * t], h[4 * t + 1], h[4 * t + 2], h[4 * t + 3]);
                *(uint4*)(Crow + j * 32 + t * 8) = v;
            }
        }
    }
    __syncthreads();
    if (wid == 0) {
        asm volatile("tcgen05.dealloc.cta_group::1.sync.aligned.b32 %0, %1;"
                     :: "r"(tb), "r"(256u));
    }
#else
    size_t m0 = (size_t)blockIdx.x * 128;
    int tid = threadIdx.x;
    for (int e = tid; e < 128 * 256; e += 256) {
        int r = e >> 8, n = e & 255;
        float acc = 0.f;
        for (int k = 0; k < DIM; k++)
            acc += A[(m0 + r) * DIM + k] * W[k * DIM + n];
        g_mappedh[(m0 + r) * DIM + n] = __float2half(acc);
    }
#endif
}

// ---------------- k_caps: softmax + Z + squash, fp16 4x16KB TMA ring ------
// stage = 32 rows x 512 B = 16 KB (restores R8's in-flight byte depth).
#define STG_ROWS 32
#define STG_B    16384
#define CR_RING 128
#define CR_W    (CR_RING + 4 * STG_B)      // 65664
#define CR_RED  (CR_W + SEQL * NCAPS * 4)  // 72064
#define CR_SC   (CR_RED + 256)             // 72320
#define CAPS_SM_BYTES (CR_SC + 64)         // 72384

__global__ __launch_bounds__(256, 3) void k_caps(const int* __restrict__ seq_len,
                                                 float* __restrict__ out) {
    extern __shared__ __align__(16) char dsm[];
    uint32_t sbase = smem_u32(dsm);
    float* sm_w   = (float*)(dsm + CR_W);
    float* sm_red = (float*)(dsm + CR_RED);
    float* sm_sc  = (float*)(dsm + CR_SC);

    int b = blockIdx.x;
    int tid = threadIdx.x;
    int warp = tid >> 5, lane = tid & 31;
    int seq = seq_len[b];
    int nblk = (seq + STG_ROWS - 1) / STG_ROWS;   // <= 7
    const __half* __restrict__ mbp = g_mappedh + (size_t)b * (SEQL * DIM);

    if (tid == 0) {
#pragma unroll
        for (int s = 0; s < 4; s++) mbar_init(sbase + s * 8, 1u);
    }
    __syncthreads();
    if (tid == 0) {
        int pre = nblk < 3 ? nblk : 3;
        for (int s = 0; s < pre; s++) {
            int rows = seq - s * STG_ROWS; if (rows > STG_ROWS) rows = STG_ROWS;
            uint32_t bytes = (uint32_t)rows * 512u;
            mbar_expect_tx(sbase + s * 8, bytes);
            tma_1d(sbase + CR_RING + s * STG_B, mbp + (size_t)s * STG_ROWS * 256,
                   bytes, sbase + s * 8);
        }
    }

    // ---- masked softmax (overlaps TMA) ----
    {
        int k = warp;
        float vals[7];
        float mx = -INFINITY;
#pragma unroll
        for (int j = 0; j < 7; j++) {
            int l = lane + 32 * j;
            float v = (l < seq) ? g_logits[k * SEQL + l] : -INFINITY;
            vals[j] = v;
            mx = fmaxf(mx, v);
        }
#pragma unroll
        for (int off = 16; off; off >>= 1)
            mx = fmaxf(mx, __shfl_xor_sync(0xffffffffu, mx, off));
        float s = 0.f;
#pragma unroll
        for (int j = 0; j < 7; j++) {
            float e = expf(vals[j] - mx);
            vals[j] = e;
            s += e;
        }
#pragma unroll
        for (int off = 16; off; off >>= 1)
            s += __shfl_xor_sync(0xffffffffu, s, off);
        float inv = 1.f / s;
#pragma unroll
        for (int j = 0; j < 7; j++) {
            int l = lane + 32 * j;
            if (l < SEQL) sm_w[l * NCAPS + k] = vals[j] * inv;
        }
    }
    __syncthreads();

    // ---- Z from fp16 SMEM ring ----
    ull z2[4] = {0ULL, 0ULL, 0ULL, 0ULL};
    for (int blk = 0; blk < nblk; blk++) {
        mbar_wait(sbase + (blk & 3) * 8, (uint32_t)((blk >> 2) & 1));
        const __half* st = (const __half*)(dsm + CR_RING + (blk & 3) * STG_B);
        int base = blk * STG_ROWS;
        int rows = seq - base; if (rows > STG_ROWS) rows = STG_ROWS;
        if (rows == STG_ROWS) {
#pragma unroll 8
            for (int r = 0; r < STG_ROWS; r++) {
                ull md = dup2(__half2float(st[r * 256 + tid]));
                ulonglong2 wa = *(const ulonglong2*)&sm_w[(base + r) * NCAPS];
                ulonglong2 wb = *(const ulonglong2*)&sm_w[(base + r) * NCAPS + 4];
                z2[0] = ffma2(md, wa.x, z2[0]);
                z2[1] = ffma2(md, wa.y, z2[1]);
                z2[2] = ffma2(md, wb.x, z2[2]);
                z2[3] = ffma2(md, wb.y, z2[3]);
            }
        } else {
            for (int r = 0; r < rows; r++) {
                ull md = dup2(__half2float(st[r * 256 + tid]));
                ulonglong2 wa = *(const ulonglong2*)&sm_w[(base + r) * NCAPS];
                ulonglong2 wb = *(const ulonglong2*)&sm_w[(base + r) * NCAPS + 4];
                z2[0] = ffma2(md, wa.x, z2[0]);
                z2[1] = ffma2(md, wa.y, z2[1]);
                z2[2] = ffma2(md, wb.x, z2[2]);
                z2[3] = ffma2(md, wb.y, z2[3]);
            }
        }
        __syncthreads();
        int nb = blk + 3;
        if (tid == 0 && nb < nblk) {
            int rows2 = seq - nb * STG_ROWS; if (rows2 > STG_ROWS) rows2 = STG_ROWS;
            uint32_t bytes = (uint32_t)rows2 * 512u;
            mbar_expect_tx(sbase + (nb & 3) * 8, bytes);
            tma_1d(sbase + CR_RING + (nb & 3) * STG_B,
                   mbp + (size_t)nb * STG_ROWS * 256, bytes, sbase + (nb & 3) * 8);
        }
    }

    float z[8];
    {
        float2 f;
        f = unpack2(z2[0]); z[0] = f.x; z[1] = f.y;
        f = unpack2(z2[1]); z[2] = f.x; z[3] = f.y;
        f = unpack2(z2[2]); z[4] = f.x; z[5] = f.y;
        f = unpack2(z2[3]); z[6] = f.x; z[7] = f.y;
    }

    // ---- squash ----
    {
        float zs[8];
#pragma unroll
        for (int k = 0; k < 8; k++) zs[k] = z[k] * z[k];
#pragma unroll
        for (int off = 16; off; off >>= 1)
#pragma unroll
            for (int k = 0; k < 8; k++)
                zs[k] += __shfl_xor_sync(0xffffffffu, zs[k], off);
        if (lane == 0) {
#pragma unroll
            for (int k = 0; k < 8; k++) sm_red[k * 8 + warp] = zs[k];
        }
    }
    __syncthreads();
    if (tid < 8) {
        float sq = 0.f;
#pragma unroll
        for (int w = 0; w < 8; w++) sq += sm_red[tid * 8 + w];
        sm_sc[tid] = sq / (1.f + sq) / sqrtf(sq + 1e-8f);
    }
    __syncthreads();

#pragma unroll
    for (int k = 0; k < 8; k++)
        out[((size_t)b * NCAPS + k) * DIM + tid] = sm_sc[k] * z[k];
}

// ---------------- k_delta: fp16-stream delta partials, 32-row stages ------
#define DELTA_SM_BYTES (CR_RING + 4 * STG_B)   // 65664
#define DNBLK 7   // 6 x 32 + 1 x 8

__global__ __launch_bounds__(256, 3) void k_delta(const float* __restrict__ caps) {
    extern __shared__ __align__(16) char dsm[];
    uint32_t sbase = smem_u32(dsm);

    int b = blockIdx.x;
    int tid = threadIdx.x;
    int warp = tid >> 5, lane = tid & 31;
    int kbase = (warp >> 2) * 4;
    int lphase = warp & 3;
    const __half* __restrict__ mbp = g_mappedh + (size_t)b * (SEQL * DIM);
    const float* __restrict__ cb = caps + (size_t)b * (NCAPS * DIM);

    if (tid == 0) {
#pragma unroll
        for (int s = 0; s < 4; s++) mbar_init(sbase + s * 8, 1u);
    }
    __syncthreads();
    if (tid == 0) {
        for (int s = 0; s < 3; s++) {
            int rows = SEQL - s * STG_ROWS; if (rows > STG_ROWS) rows = STG_ROWS;
            uint32_t bytes = (uint32_t)rows * 512u;
            mbar_expect_tx(sbase + s * 8, bytes);
            tma_1d(sbase + CR_RING + s * STG_B, mbp + (size_t)s * STG_ROWS * 256,
                   bytes, sbase + s * 8);
        }
    }

    // caps for 4 owned capsules as f32x2 pairs
    ull c2[4][4];
#pragma unroll
    for (int k = 0; k < 4; k++) {
        ulonglong2 ca = *(const ulonglong2*)&cb[(kbase + k) * DIM + lane * 8];
        ulonglong2 cv = *(const ulonglong2*)&cb[(kbase + k) * DIM + lane * 8 + 4];
        c2[k][0] = ca.x; c2[k][1] = ca.y; c2[k][2] = cv.x; c2[k][3] = cv.y;
    }

    bool writer = (lane & 7) == 0;
    int kw = kbase + ((lane >> 4) & 1) * 2 + ((lane >> 3) & 1);

    for (int blk = 0; blk < DNBLK; blk++) {
        mbar_wait(sbase + (blk & 3) * 8, (uint32_t)((blk >> 2) & 1));
        const __half* st = (const __half*)(dsm + CR_RING + (blk & 3) * STG_B);
        int base = blk * STG_ROWS;
        int rcnt = SEQL - base; if (rcnt > STG_ROWS) rcnt = STG_ROWS;
#pragma unroll
        for (int r0 = 0; r0 < STG_ROWS; r0 += 4) {
            int r = r0 + lphase;
            if (r >= rcnt) break;
            uint4 hv = *(const uint4*)&st[r * 256 + lane * 8];
            const __half2* hp = (const __half2*)&hv;
            float2 f0 = __half22float2(hp[0]);
            float2 f1 = __half22float2(hp[1]);
            float2 f2 = __half22float2(hp[2]);
            float2 f3 = __half22float2(hp[3]);
            ull m0x = packf2(f0.x, f0.y);
            ull m0y = packf2(f1.x, f1.y);
            ull m1x = packf2(f2.x, f2.y);
            ull m1y = packf2(f3.x, f3.y);
            float p[4];
#pragma unroll
            for (int k = 0; k < 4; k++) {
                ull acc = 0ULL;
                acc = ffma2(c2[k][0], m0x, acc);
                acc = ffma2(c2[k][1], m0y, acc);
                acc = ffma2(c2[k][2], m1x, acc);
                acc = ffma2(c2[k][3], m1y, acc);
                float2 f = unpack2(acc);
                p[k] = f.x + f.y;
            }
            bool hi4 = (lane & 16) != 0;
            float t0 = hi4 ? p[0] : p[2];
            float t1 = hi4 ? p[1] : p[3];
            t0 = __shfl_xor_sync(0xffffffffu, t0, 16);
            t1 = __shfl_xor_sync(0xffffffffu, t1, 16);
            float q0 = (hi4 ? p[2] : p[0]) + t0;
            float q1 = (hi4 ? p[3] : p[1]) + t1;
            bool hi3 = (lane & 8) != 0;
            float t = hi3 ? q0 : q1;
            t = __shfl_xor_sync(0xffffffffu, t, 8);
            float rr = (hi3 ? q1 : q0) + t;
            rr += __shfl_xor_sync(0xffffffffu, rr, 4);
            rr += __shfl_xor_sync(0xffffffffu, rr, 2);
            rr += __shfl_xor_sync(0xffffffffu, rr, 1);
            if (writer)
                g_part[((size_t)kw * SEQL + base + r) * NBATCH + b] = rr;
        }
        __syncthreads();
        int nb = blk + 3;
        if (tid == 0 && nb < DNBLK) {
            int rows2 = SEQL - nb * STG_ROWS; if (rows2 > STG_ROWS) rows2 = STG_ROWS;
            uint32_t bytes = (uint32_t)rows2 * 512u;
            mbar_expect_tx(sbase + (nb & 3) * 8, bytes);
            tma_1d(sbase + CR_RING + (nb & 3) * STG_B,
                   mbp + (size_t)nb * STG_ROWS * 256, bytes, sbase + (nb & 3) * 8);
        }
    }
}

// ---------------- deterministic batch-reduce of delta into logits --------
__global__ __launch_bounds__(256) void k_update() {
    __shared__ float red[256];
    int i = blockIdx.x;  // 0..1599
    const float4* row = (const float4*)(g_part + (size_t)i * NBATCH);
    float4 v = row[threadIdx.x];
    red[threadIdx.x] = v.x + v.y + v.z + v.w;
    __syncthreads();
#pragma unroll
    for (int st = 128; st; st >>= 1) {
        if (threadIdx.x < st) red[threadIdx.x] += red[threadIdx.x + st];
        __syncthreads();
    }
    if (threadIdx.x == 0) g_logits[i] += red[0];
}

// ---------------- launch --------------------------------------------------
extern "C" void kernel_launch(void* const* d_in, const int* in_sizes, int n_in,
                              void* d_out, int out_size) {
    const float* emb  = (const float*)d_in[0];
    const int*   seq  = (const int*)d_in[1];
    const float* rlog = (const float*)d_in[2];
    const float* W    = (const float*)d_in[3];
    float* out = (float*)d_out;

    cudaFuncSetAttribute(k_gemm_tc, cudaFuncAttributeMaxDynamicSharedMemorySize,
                         GSM_BYTES);
    cudaFuncSetAttribute(k_caps, cudaFuncAttributeMaxDynamicSharedMemorySize,
                         CAPS_SM_BYTES);
    cudaFuncSetAttribute(k_delta, cudaFuncAttributeMaxDynamicSharedMemorySize,
                         DELTA_SM_BYTES);

    k_init<<<(NCAPS * SEQL + 255) / 256, 256>>>(rlog);
    k_convW<<<DIM, DIM>>>(W);
    k_gemm_tc<<<(NBATCH * SEQL) / 128, 256, GSM_BYTES>>>(emb, W);

    for (int it = 0; it < 3; it++) {
        k_caps<<<NBATCH, 256, CAPS_SM_BYTES>>>(seq, out);
        if (it < 2) {
            k_delta<<<NBATCH, 256, DELTA_SM_BYTES>>>(out);
            k_update<<<NCAPS * SEQL, 256>>>();
        }
    }
}

// round 16
// speedup vs baseline: 1.5122x; 1.0442x over previous
#include <cuda_runtime.h>
#include <cuda_bf16.h>
#include <cuda_fp16.h>
#include <math.h>
#include <stdint.h>

typedef unsigned long long ull;

#define NBATCH 1024
#define SEQL   200
#define DIM    256
#define NCAPS  8

#if !defined(__CUDA_ARCH__) || defined(__CUDA_ARCH_FEAT_SM103_ALL) || \
    defined(__CUDA_ARCH_FEAT_SM100_ALL) || defined(__CUDA_ARCH_FEAT_SM101_ALL)
#define TC_OK 1
#else
#define TC_OK 0
#endif

// ---------------- device scratch (no allocations allowed) ----------------
__device__ __half g_mappedh[(size_t)NBATCH * SEQL * DIM]; // 104.9 MB fp16
__device__ float g_logits[NCAPS * SEQL];
__device__ float g_part[(size_t)NCAPS * SEQL * NBATCH];   // [k*L][b]
__device__ __nv_bfloat16 g_WhT[DIM * DIM];
__device__ __nv_bfloat16 g_WlT[DIM * DIM];

// ---------------- f32x2 helpers ------------------------------------------
__device__ __forceinline__ ull ffma2(ull a, ull b, ull c) {
    ull d;
    asm("fma.rn.f32x2 %0, %1, %2, %3;" : "=l"(d) : "l"(a), "l"(b), "l"(c));
    return d;
}
__device__ __forceinline__ ull dup2(float x) {
    ull d;
    asm("mov.b64 %0, {%1, %1};" : "=l"(d) : "f"(x));
    return d;
}
__device__ __forceinline__ ull packf2(float a, float b) {
    ull d;
    asm("mov.b64 %0, {%1, %2};" : "=l"(d) : "f"(a), "f"(b));
    return d;
}
__device__ __forceinline__ float2 unpack2(ull a) {
    float2 f;
    asm("mov.b64 {%0, %1}, %2;" : "=f"(f.x), "=f"(f.y) : "l"(a));
    return f;
}

// ---------------- smem/mbarrier/TMA helpers (baseline PTX) ----------------
__device__ __forceinline__ uint32_t smem_u32(const void* p) {
    uint32_t a;
    asm("{ .reg .u64 t; cvta.to.shared.u64 t, %1; cvt.u32.u64 %0, t; }"
        : "=r"(a) : "l"(p));
    return a;
}
__device__ __forceinline__ void mbar_init(uint32_t a, uint32_t cnt) {
    asm volatile("mbarrier.init.shared.b64 [%0], %1;" :: "r"(a), "r"(cnt) : "memory");
}
__device__ __forceinline__ void mbar_expect_tx(uint32_t a, uint32_t bytes) {
    asm volatile("mbarrier.arrive.expect_tx.shared.b64 _, [%0], %1;"
                 :: "r"(a), "r"(bytes) : "memory");
}
__device__ __forceinline__ void tma_1d(uint32_t dst, const void* src,
                                       uint32_t bytes, uint32_t mbar) {
    asm volatile(
        "cp.async.bulk.shared::cluster.global.mbarrier::complete_tx::bytes "
        "[%0], [%1], %2, [%3];"
        :: "r"(dst), "l"(src), "r"(bytes), "r"(mbar) : "memory");
}
__device__ __forceinline__ void mbar_wait(uint32_t a, uint32_t par) {
    asm volatile(
        "{\n\t.reg .pred P;\n"
        "W%=:\n\t"
        "mbarrier.try_wait.parity.acquire.cta.shared::cta.b64 P, [%0], %1, 0x989680;\n\t"
        "@P bra D%=;\n\t"
        "bra W%=;\n"
        "D%=:\n\t}" :: "r"(a), "r"(par) : "memory");
}

#if TC_OK
__device__ __forceinline__ uint32_t elect1() {
    uint32_t p;
    asm volatile("{ .reg .pred p; elect.sync _|p, 0xFFFFFFFF; selp.b32 %0,1,0,p; }"
                 : "=r"(p));
    return p;
}
__device__ __forceinline__ void mma_f16_ss(uint32_t d, uint64_t a, uint64_t b,
                                           uint32_t id, uint32_t en) {
    asm volatile(
        "{\n\t.reg .pred p;\n\tsetp.ne.u32 p, %5, 0;\n\t"
        "tcgen05.mma.cta_group::1.kind::f16 [%0], %1, %2, %3, {%4,%4,%4,%4}, p;\n\t}"
        :: "r"(d), "l"(a), "l"(b), "r"(id), "r"(0u), "r"(en) : "memory");
}
#define LDTM_X32(r, addr) \
    asm volatile( \
        "tcgen05.ld.sync.aligned.32x32b.x32.b32 " \
        "{%0,%1,%2,%3,%4,%5,%6,%7,%8,%9,%10,%11,%12,%13,%14,%15," \
        "%16,%17,%18,%19,%20,%21,%22,%23,%24,%25,%26,%27,%28,%29,%30,%31}, [%32];" \
        : "=r"((r)[0]),"=r"((r)[1]),"=r"((r)[2]),"=r"((r)[3]), \
          "=r"((r)[4]),"=r"((r)[5]),"=r"((r)[6]),"=r"((r)[7]), \
          "=r"((r)[8]),"=r"((r)[9]),"=r"((r)[10]),"=r"((r)[11]), \
          "=r"((r)[12]),"=r"((r)[13]),"=r"((r)[14]),"=r"((r)[15]), \
          "=r"((r)[16]),"=r"((r)[17]),"=r"((r)[18]),"=r"((r)[19]), \
          "=r"((r)[20]),"=r"((r)[21]),"=r"((r)[22]),"=r"((r)[23]), \
          "=r"((r)[24]),"=r"((r)[25]),"=r"((r)[26]),"=r"((r)[27]), \
          "=r"((r)[28]),"=r"((r)[29]),"=r"((r)[30]),"=r"((r)[31]) \
        : "r"(addr))
#endif  // TC_OK

// ---------------- init kernels -------------------------------------------
__global__ void k_init(const float* __restrict__ rlog) {
    int i = blockIdx.x * blockDim.x + threadIdx.x;
    if (i < NCAPS * SEQL) g_logits[i] = rlog[i];
}

__global__ void k_convW(const float* __restrict__ W) {
    int k = blockIdx.x;
    int n = threadIdx.x;
    float v = W[k * DIM + n];
    __nv_bfloat16 h = __float2bfloat16(v);
    float r = v - __bfloat162float(h);
    g_WhT[n * DIM + k] = h;
    g_WlT[n * DIM + k] = __float2bfloat16(r);
}

// ---------------- tensor-core GEMM: g_mappedh = fp16(A @ W) ---------------
#define OFF_AH 1024
#define OFF_AL 17408
#define OFF_BH 33792
#define OFF_BL 66560
#define GSM_BYTES 99328

__global__ __launch_bounds__(256, 2) void k_gemm_tc(const float* __restrict__ A,
                                                    const float* __restrict__ W) {
#if TC_OK
    extern __shared__ __align__(16) float sm[];
    char* sb = (char*)sm;
    uint32_t sbase = smem_u32(sm);
    int tid = threadIdx.x, wid = tid >> 5;
    size_t m0 = (size_t)blockIdx.x * 128;

    if (wid == 0) {
        asm volatile("tcgen05.alloc.cta_group::1.sync.aligned.shared::cta.b32 [%0], %1;"
                     :: "r"(sbase), "r"(256u) : "memory");
        asm volatile("tcgen05.relinquish_alloc_permit.cta_group::1.sync.aligned;");
    }
    __syncthreads();
    uint32_t tb;
    asm volatile("ld.shared.b32 %0, [%1];" : "=r"(tb) : "r"(sbase));

    if (tid == 0) mbar_init(sbase + 8, 1u);
    __syncthreads();

    const uint64_t DB = (2ULL << 61) | (1ULL << 46) | (64ULL << 32) | (1ULL << 16);
    uint64_t dAh = DB | (((uint64_t)(sbase + OFF_AH) >> 4) & 0x3FFF);
    uint64_t dAl = DB | (((uint64_t)(sbase + OFF_AL) >> 4) & 0x3FFF);
    uint64_t dBh = DB | (((uint64_t)(sbase + OFF_BH) >> 4) & 0x3FFF);
    uint64_t dBl = DB | (((uint64_t)(sbase + OFF_BL) >> 4) & 0x3FFF);
    const uint32_t idesc = (1u << 4) | (1u << 7) | (1u << 10) |
                           ((DIM / 8) << 17) | ((128 / 16) << 24);

    float4 fA[8];
#pragma unroll
    for (int i = 0; i < 8; i++) {
        int idx = tid + i * 256;
        int r = idx >> 4, c4 = idx & 15;
        fA[i] = *(const float4*)(A + (m0 + r) * DIM + 0 + c4 * 4);
    }

    uint32_t first = 0;
    for (int c = 0; c < 4; c++) {
        int k0 = c * 64;
#pragma unroll
        for (int i = 0; i < 8; i++) {
            int idx = tid + i * 256;
            int r = idx >> 4, c4 = idx & 15;
            float4 f = fA[i];
            __nv_bfloat16 h0 = __float2bfloat16(f.x), h1 = __float2bfloat16(f.y),
                          h2 = __float2bfloat16(f.z), h3 = __float2bfloat16(f.w);
            float l0 = f.x - __bfloat162float(h0), l1 = f.y - __bfloat162float(h1),
                  l2 = f.z - __bfloat162float(h2), l3 = f.w - __bfloat162float(h3);
            uint32_t off = r * 128 + c4 * 8;
            uint32_t sw = off ^ ((off >> 3) & 0x70);
            uint2 uh, ulv;
            uh.x = ((uint32_t)__bfloat16_as_ushort(h1) << 16) | __bfloat16_as_ushort(h0);
            uh.y = ((uint32_t)__bfloat16_as_ushort(h3) << 16) | __bfloat16_as_ushort(h2);
            __nv_bfloat16 q0 = __float2bfloat16(l0), q1 = __float2bfloat16(l1),
                          q2 = __float2bfloat16(l2), q3 = __float2bfloat16(l3);
            ulv.x = ((uint32_t)__bfloat16_as_ushort(q1) << 16) | __bfloat16_as_ushort(q0);
            ulv.y = ((uint32_t)__bfloat16_as_ushort(q3) << 16) | __bfloat16_as_ushort(q2);
            *(uint2*)(sb + OFF_AH + sw) = uh;
            *(uint2*)(sb + OFF_AL + sw) = ulv;
        }
#pragma unroll
        for (int i = 0; i < 8; i++) {
            int idx = tid + i * 256;
            int r = idx >> 3, cc = idx & 7;
            uint32_t off = r * 128 + cc * 16;
            uint32_t sw = off ^ ((off >> 3) & 0x70);
            uint4 vh = *(const uint4*)((const char*)g_WhT + r * 512 + k0 * 2 + cc * 16);
            uint4 vl = *(const uint4*)((const char*)g_WlT + r * 512 + k0 * 2 + cc * 16);
            *(uint4*)(sb + OFF_BH + sw) = vh;
            *(uint4*)(sb + OFF_BL + sw) = vl;
        }
        __syncthreads();
        if (wid == 0) {
            asm volatile("fence.proxy.async.shared::cta;" ::: "memory");
            if (elect1()) {
#pragma unroll
                for (int s = 0; s < 4; s++) {
                    mma_f16_ss(tb, dAh + s * 2, dBh + s * 2, idesc, first);
                    first = 1;
                    mma_f16_ss(tb, dAh + s * 2, dBl + s * 2, idesc, 1);
                    mma_f16_ss(tb, dAl + s * 2, dBh + s * 2, idesc, 1);
                }
                asm volatile(
                    "tcgen05.commit.cta_group::1.mbarrier::arrive::one.shared::cluster.b64 [%0];"
                    :: "r"(sbase + 8) : "memory");
            }
        }
        if (c < 3) {
            int kn = k0 + 64;
#pragma unroll
            for (int i = 0; i < 8; i++) {
                int idx = tid + i * 256;
                int r = idx >> 4, c4 = idx & 15;
                fA[i] = *(const float4*)(A + (m0 + r) * DIM + kn + c4 * 4);
            }
        }
        mbar_wait(sbase + 8, (uint32_t)(c & 1));
    }

    asm volatile("tcgen05.fence::after_thread_sync;" ::: "memory");
    if (tid < 128) {
        __half* Crow = g_mappedh + (m0 + tid) * DIM;
#pragma unroll
        for (int j = 0; j < 8; j++) {
            uint32_t r[32];
            LDTM_X32(r, tb + j * 32);
            asm volatile("tcgen05.wait::ld.sync.aligned;" ::: "memory");
            uint32_t h[16];
#pragma unroll
            for (int q = 0; q < 16; q++) {
                __half2 hv = __floats2half2_rn(__uint_as_float(r[2 * q]),
                                               __uint_as_float(r[2 * q + 1]));
                h[q] = *(uint32_t*)&hv;
            }
#pragma unroll
            for (int t = 0; t < 4; t++) {
                uint4 v = make_uint4(h[4 * t], h[4 * t + 1], h[4 * t + 2], h[4 * t + 3]);
                *(uint4*)(Crow + j * 32 + t * 8) = v;
            }
        }
    }
    __syncthreads();
    if (wid == 0) {
        asm volatile("tcgen05.dealloc.cta_group::1.sync.aligned.b32 %0, %1;"
                     :: "r"(tb), "r"(256u));
    }
#else
    size_t m0 = (size_t)blockIdx.x * 128;
    int tid = threadIdx.x;
    for (int e = tid; e < 128 * 256; e += 256) {
        int r = e >> 8, n = e & 255;
        float acc = 0.f;
        for (int k = 0; k < DIM; k++)
            acc += A[(m0 + r) * DIM + k] * W[k * DIM + n];
        g_mappedh[(m0 + r) * DIM + n] = __float2half(acc);
    }
#endif
}

// ---------------- k_fcaps: fused iteration, fp16 tile resident, occ 2 -----
// 7 stages x 32 rows x 512 B (last stage 8 rows). All stages burst up front;
// Z consumes as they land; delta reads the resident ring (no DRAM re-read).
// layout: mbars[0,128) | ring@128 (102400) | w fp32 | caps fp16 | red | sc
#define FST      7
#define FSTG_ROWS 32
#define FSTG_B   16384
#define FB_RING  128
#define FB_W     (FB_RING + 102400)        // 102528
#define FB_CAPS  (FB_W + SEQL * NCAPS * 4) // 108928
#define FB_RED   (FB_CAPS + NCAPS * DIM * 2) // 113024
#define FB_SC    (FB_RED + 256)            // 113280
#define FB_BYTES (FB_SC + 32)              // 113312 (x2 = 226624 <= 228KB)

__global__ __launch_bounds__(256, 2) void k_fcaps(const int* __restrict__ seq_len,
                                                  float* __restrict__ out,
                                                  int do_delta) {
    extern __shared__ __align__(16) char dsm[];
    uint32_t sbase = smem_u32(dsm);
    float*  sm_w    = (float*)(dsm + FB_W);
    __half* sm_caps = (__half*)(dsm + FB_CAPS);
    float*  sm_red  = (float*)(dsm + FB_RED);
    float*  sm_sc   = (float*)(dsm + FB_SC);

    int b = blockIdx.x;
    int tid = threadIdx.x;
    int warp = tid >> 5, lane = tid & 31;
    int seq = seq_len[b];
    int nblkZ = (seq + FSTG_ROWS - 1) / FSTG_ROWS;   // <= 7
    int nIssue = do_delta ? FST : nblkZ;
    const __half* __restrict__ mbp = g_mappedh + (size_t)b * (SEQL * DIM);

    if (tid == 0) {
#pragma unroll
        for (int s = 0; s < FST; s++) mbar_init(sbase + s * 8, 1u);
    }
    __syncthreads();
    if (tid == 0) {
        int lim = do_delta ? SEQL : seq;
        for (int s = 0; s < nIssue; s++) {
            int rows = lim - s * FSTG_ROWS; if (rows > FSTG_ROWS) rows = FSTG_ROWS;
            uint32_t bytes = (uint32_t)rows * 512u;
            mbar_expect_tx(sbase + s * 8, bytes);
            tma_1d(sbase + FB_RING + s * FSTG_B,
                   mbp + (size_t)s * FSTG_ROWS * 256, bytes, sbase + s * 8);
        }
    }

    // ---- masked softmax (overlaps TMA burst) ----
    {
        int k = warp;
        float vals[7];
        float mx = -INFINITY;
#pragma unroll
        for (int j = 0; j < 7; j++) {
            int l = lane + 32 * j;
            float v = (l < seq) ? g_logits[k * SEQL + l] : -INFINITY;
            vals[j] = v;
            mx = fmaxf(mx, v);
        }
#pragma unroll
        for (int off = 16; off; off >>= 1)
            mx = fmaxf(mx, __shfl_xor_sync(0xffffffffu, mx, off));
        float s = 0.f;
#pragma unroll
        for (int j = 0; j < 7; j++) {
            float e = expf(vals[j] - mx);
            vals[j] = e;
            s += e;
        }
#pragma unroll
        for (int off = 16; off; off >>= 1)
            s += __shfl_xor_sync(0xffffffffu, s, off);
        float inv = 1.f / s;
#pragma unroll
        for (int j = 0; j < 7; j++) {
            int l = lane + 32 * j;
            if (l < SEQL) sm_w[l * NCAPS + k] = vals[j] * inv;
        }
    }
    __syncthreads();

    // ---- Z: consume stages as they land (single-use, parity 0) ----
    ull z2[4] = {0ULL, 0ULL, 0ULL, 0ULL};
    for (int blk = 0; blk < nblkZ; blk++) {
        mbar_wait(sbase + blk * 8, 0u);
        const __half* st = (const __half*)(dsm + FB_RING + blk * FSTG_B);
        int base = blk * FSTG_ROWS;
        int rows = seq - base; if (rows > FSTG_ROWS) rows = FSTG_ROWS;
        if (rows == FSTG_ROWS) {
#pragma unroll 8
            for (int r = 0; r < FSTG_ROWS; r++) {
                ull md = dup2(__half2float(st[r * 256 + tid]));
                ulonglong2 wa = *(const ulonglong2*)&sm_w[(base + r) * NCAPS];
                ulonglong2 wb = *(const ulonglong2*)&sm_w[(base + r) * NCAPS + 4];
                z2[0] = ffma2(md, wa.x, z2[0]);
                z2[1] = ffma2(md, wa.y, z2[1]);
                z2[2] = ffma2(md, wb.x, z2[2]);
                z2[3] = ffma2(md, wb.y, z2[3]);
            }
        } else {
            for (int r = 0; r < rows; r++) {
                ull md = dup2(__half2float(st[r * 256 + tid]));
                ulonglong2 wa = *(const ulonglong2*)&sm_w[(base + r) * NCAPS];
                ulonglong2 wb = *(const ulonglong2*)&sm_w[(base + r) * NCAPS + 4];
                z2[0] = ffma2(md, wa.x, z2[0]);
                z2[1] = ffma2(md, wa.y, z2[1]);
                z2[2] = ffma2(md, wb.x, z2[2]);
                z2[3] = ffma2(md, wb.y, z2[3]);
            }
        }
    }

    float z[8];
    {
        float2 f;
        f = unpack2(z2[0]); z[0] = f.x; z[1] = f.y;
        f = unpack2(z2[1]); z[2] = f.x; z[3] = f.y;
        f = unpack2(z2[2]); z[4] = f.x; z[5] = f.y;
        f = unpack2(z2[3]); z[6] = f.x; z[7] = f.y;
    }

    // ---- squash ----
    {
        float zs[8];
#pragma unroll
        for (int k = 0; k < 8; k++) zs[k] = z[k] * z[k];
#pragma unroll
        for (int off = 16; off; off >>= 1)
#pragma unroll
            for (int k = 0; k < 8; k++)
                zs[k] += __shfl_xor_sync(0xffffffffu, zs[k], off);
        if (lane == 0) {
#pragma unroll
            for (int k = 0; k < 8; k++) sm_red[k * 8 + warp] = zs[k];
        }
    }
    __syncthreads();
    if (tid < 8) {
        float sq = 0.f;
#pragma unroll
        for (int w = 0; w < 8; w++) sq += sm_red[tid * 8 + w];
        sm_sc[tid] = sq / (1.f + sq) / sqrtf(sq + 1e-8f);
    }
    __syncthreads();

    if (!do_delta) {
        // final iteration: write output capsules and exit
#pragma unroll
        for (int k = 0; k < 8; k++)
            out[((size_t)b * NCAPS + k) * DIM + tid] = sm_sc[k] * z[k];
        return;
    }

    // caps -> SMEM fp16 for the delta phase
#pragma unroll
    for (int k = 0; k < 8; k++)
        sm_caps[k * DIM + tid] = __float2half(sm_sc[k] * z[k]);

    // wait for stages beyond seq (delta needs all 200 rows)
    for (int s = nblkZ; s < FST; s++) mbar_wait(sbase + s * 8, 0u);
    __syncthreads();

    // ---- delta from resident fp16 ring: warp owns 4 caps, l-stripe mod 4 --
    {
        int kbase = (warp >> 2) * 4;
        int lphase = warp & 3;

        ull c2[4][4];
#pragma unroll
        for (int k = 0; k < 4; k++) {
            uint4 hv = *(const uint4*)&sm_caps[(kbase + k) * DIM + lane * 8];
            const __half2* hp = (const __half2*)&hv;
            float2 f0 = __half22float2(hp[0]);
            float2 f1 = __half22float2(hp[1]);
            float2 f2 = __half22float2(hp[2]);
            float2 f3 = __half22float2(hp[3]);
            c2[k][0] = packf2(f0.x, f0.y);
            c2[k][1] = packf2(f1.x, f1.y);
            c2[k][2] = packf2(f2.x, f2.y);
            c2[k][3] = packf2(f3.x, f3.y);
        }

        bool writer = (lane & 7) == 0;
        int kw = kbase + ((lane >> 4) & 1) * 2 + ((lane >> 3) & 1);
        const __half* ring = (const __half*)(dsm + FB_RING);

        for (int l = lphase; l < SEQL; l += 4) {
            uint4 hv = *(const uint4*)&ring[l * 256 + lane * 8];
            const __half2* hp = (const __half2*)&hv;
            float2 f0 = __half22float2(hp[0]);
            float2 f1 = __half22float2(hp[1]);
            float2 f2 = __half22float2(hp[2]);
            float2 f3 = __half22float2(hp[3]);
            ull m0 = packf2(f0.x, f0.y);
            ull m1 = packf2(f1.x, f1.y);
            ull m2 = packf2(f2.x, f2.y);
            ull m3 = packf2(f3.x, f3.y);
            float p[4];
#pragma unroll
            for (int k = 0; k < 4; k++) {
                ull acc = 0ULL;
                acc = ffma2(c2[k][0], m0, acc);
                acc = ffma2(c2[k][1], m1, acc);
                acc = ffma2(c2[k][2], m2, acc);
                acc = ffma2(c2[k][3], m3, acc);
                float2 f = unpack2(acc);
                p[k] = f.x + f.y;
            }
            bool hi4 = (lane & 16) != 0;
            float t0 = hi4 ? p[0] : p[2];
            float t1 = hi4 ? p[1] : p[3];
            t0 = __shfl_xor_sync(0xffffffffu, t0, 16);
            t1 = __shfl_xor_sync(0xffffffffu, t1, 16);
            float q0 = (hi4 ? p[2] : p[0]) + t0;
            float q1 = (hi4 ? p[3] : p[1]) + t1;
            bool hi3 = (lane & 8) != 0;
            float t = hi3 ? q0 : q1;
            t = __shfl_xor_sync(0xffffffffu, t, 8);
            float rr = (hi3 ? q1 : q0) + t;
            rr += __shfl_xor_sync(0xffffffffu, rr, 4);
            rr += __shfl_xor_sync(0xffffffffu, rr, 2);
            rr += __shfl_xor_sync(0xffffffffu, rr, 1);
            if (writer)
                g_part[((size_t)kw * SEQL + l) * NBATCH + b] = rr;
        }
    }
}

// ---------------- deterministic batch-reduce of delta into logits --------
__global__ __launch_bounds__(256) void k_update() {
    __shared__ float red[256];
    int i = blockIdx.x;  // 0..1599
    const float4* row = (const float4*)(g_part + (size_t)i * NBATCH);
    float4 v = row[threadIdx.x];
    red[threadIdx.x] = v.x + v.y + v.z + v.w;
    __syncthreads();
#pragma unroll
    for (int st = 128; st; st >>= 1) {
        if (threadIdx.x < st) red[threadIdx.x] += red[threadIdx.x + st];
        __syncthreads();
    }
    if (threadIdx.x == 0) g_logits[i] += red[0];
}

// ---------------- launch --------------------------------------------------
extern "C" void kernel_launch(void* const* d_in, const int* in_sizes, int n_in,
                              void* d_out, int out_size) {
    const float* emb  = (const float*)d_in[0];
    const int*   seq  = (const int*)d_in[1];
    const float* rlog = (const float*)d_in[2];
    const float* W    = (const float*)d_in[3];
    float* out = (float*)d_out;

    cudaFuncSetAttribute(k_gemm_tc, cudaFuncAttributeMaxDynamicSharedMemorySize,
                         GSM_BYTES);
    cudaFuncSetAttribute(k_fcaps, cudaFuncAttributeMaxDynamicSharedMemorySize,
                         FB_BYTES);

    k_init<<<(NCAPS * SEQL + 255) / 256, 256>>>(rlog);
    k_convW<<<DIM, DIM>>>(W);
    k_gemm_tc<<<(NBATCH * SEQL) / 128, 256, GSM_BYTES>>>(emb, W);

    for (int it = 0; it < 3; it++) {
        k_fcaps<<<NBATCH, 256, FB_BYTES>>>(seq, out, (it < 2) ? 1 : 0);
        if (it < 2) k_update<<<NCAPS * SEQL, 256>>>();
    }
}